// round 11
// baseline (speedup 1.0000x reference)
#include <cuda_runtime.h>
#include <cuda_fp16.h>
#include <math.h>
#include <stdint.h>

#define S_  32
#define T_  64
#define B_  64
#define C_  5
#define VOCAB_ 32000

// ---------------- scratch (device globals; no allocation) ----------------
__device__ float g_xg_intra[(size_t)2*S_*T_*B_*384]; // [dir][row(s,t,b)][384]
__device__ float g_intra_out[(size_t)S_*T_*B_*256];  // [s][t][b][256] fwd|bwd
__device__ float g_a1p[2*S_*T_*B_];                  // 2 partial planes
__device__ float g_sent[S_*B_*256];
__device__ float g_xg_inter[2*S_*B_*384];
__device__ float g_inter_out[S_*B_*256];
__device__ float g_a2p[2*S_*B_];
// fp16 preconversions
__device__ uint16_t g_emb_h[(size_t)VOCAB_*128];     // embed table half
__device__ uint16_t g_wihA_h[768*128];               // Wih_a half [col][k]
__device__ uint16_t g_wihE_h[768*256];               // Wih_e half [col][k]
__device__ uint16_t g_ww_h[2*256*256];               // WW_a/WW_e transposed half [n][k]

__device__ __forceinline__ float sigm(float x) { return 1.f / (1.f + expf(-x)); }

__device__ __forceinline__ uint32_t f2h2(float x, float y) {
    __half2 h = __floats2half2_rn(x, y);
    return *(uint32_t*)&h;
}
// 2-term split: hi = rn(x,y); lo = rn(residual)
__device__ __forceinline__ void split_h2(float x, float y, uint32_t& hi, uint32_t& lo) {
    __half hx = __float2half_rn(x), hy = __float2half_rn(y);
    __half lx = __float2half_rn(x - __half2float(hx));
    __half ly = __float2half_rn(y - __half2float(hy));
    hi = ((uint32_t)(*(uint16_t*)&hy) << 16) | (uint32_t)(*(uint16_t*)&hx);
    lo = ((uint32_t)(*(uint16_t*)&ly) << 16) | (uint32_t)(*(uint16_t*)&lx);
}

__device__ __forceinline__ void mma_f16(float c[4],
                                        uint32_t a0, uint32_t a1, uint32_t a2, uint32_t a3,
                                        uint32_t b0, uint32_t b1) {
    asm volatile(
        "mma.sync.aligned.m16n8k16.row.col.f32.f16.f16.f32 "
        "{%0,%1,%2,%3}, {%4,%5,%6,%7}, {%8,%9}, {%0,%1,%2,%3};"
        : "+f"(c[0]), "+f"(c[1]), "+f"(c[2]), "+f"(c[3])
        : "r"(a0), "r"(a1), "r"(a2), "r"(a3), "r"(b0), "r"(b1));
}

// ---- prep kernels: one-time fp16 conversions ------------------------------
__global__ void k_prep_h(const float* __restrict__ in, uint16_t* __restrict__ out) {
    size_t q = ((size_t)blockIdx.x * 256 + threadIdx.x) * 8;
    float4 v0 = *(const float4*)(in + q);
    float4 v1 = *(const float4*)(in + q + 4);
    uint4 u = make_uint4(f2h2(v0.x, v0.y), f2h2(v0.z, v0.w),
                         f2h2(v1.x, v1.y), f2h2(v1.z, v1.w));
    *(uint4*)(out + q) = u;
}
__global__ void k_prep_ww_h(const float* __restrict__ Wa, const float* __restrict__ We,
                            uint16_t* __restrict__ out) {
    int idx = blockIdx.x * 256 + threadIdx.x;       // 0..65535
    const float* W = blockIdx.y ? We : Wa;
    int n = idx >> 8, h = idx & 255;
    __half v = __float2half_rn(W[h * 256 + n]);
    out[blockIdx.y * 65536 + n * 256 + h] = *(uint16_t*)&v;
}

// ============ unified fp16 tensor GEMM ====================================
// C[row, col] = sum_k A[row,k] * W[col,k]   (W preconverted half [col][k])
// KDIM=128: full-K resident (1 barrier pair). KDIM=256: 4 x 64-k chunks.
template<int KDIM, bool ATTN, bool AHALF>
__global__ __launch_bounds__(256, 3) void k_gemm4(const int* __restrict__ tokens,
                                                  const void* __restrict__ Av,
                                                  const uint16_t* __restrict__ Wt,
                                                  const float* __restrict__ bias,
                                                  const float* __restrict__ proj,
                                                  float* __restrict__ out,
                                                  int nrows) {
    constexpr int CK = (KDIM == 128) ? 128 : 64;   // chunk k
    constexpr int CW = CK / 2;                      // words per row per chunk
    constexpr int CS = CW + 4;                      // smem stride (words)
    constexpr int NC = KDIM / CK;
    extern __shared__ uint32_t usm[];
    uint32_t* As = usm;               // 64 x CS
    uint32_t* Bs = usm + 64 * CS;     // 128 x CS
    __shared__ int toks[64];
    __shared__ float part_sm[4][65];
    const int rb = blockIdx.x, cb = blockIdx.y;
    const int tid = threadIdx.x;
    const int lane = tid & 31, wid = tid >> 5;
    const int wm = wid >> 2, wn = wid & 3;   // 2 (M) x 4 (N)
    const int grp = lane >> 2, t4 = lane & 3;

    if (tokens) {
        if (tid < 64) toks[tid] = tokens[rb * 64 + tid];
        __syncthreads();
    }

    float acc[2][4][4];
#pragma unroll
    for (int i = 0; i < 2; i++)
#pragma unroll
        for (int j = 0; j < 4; j++)
#pragma unroll
            for (int r = 0; r < 4; r++) acc[i][j][r] = 0.f;

#pragma unroll
    for (int kc = 0; kc < NC; kc++) {
        if (kc) __syncthreads();
        // A chunk: 64 rows x CK k
        for (int q = tid; q < 64 * (CW / 4); q += 256) {
            int r = q / (CW / 4), u = q % (CW / 4);
            size_t rowbase = tokens ? (size_t)toks[r] * KDIM
                                    : (size_t)(rb * 64 + r) * KDIM;
            if (AHALF) {
                uint4 v = *(const uint4*)((const uint16_t*)Av + rowbase + kc * CK + u * 8);
                *(uint4*)(As + r * CS + u * 4) = v;
            } else {
                const float* src = (const float*)Av + rowbase + kc * CK + u * 8;
                float4 v0 = *(const float4*)src;
                float4 v1 = *(const float4*)(src + 4);
                *(uint4*)(As + r * CS + u * 4) =
                    make_uint4(f2h2(v0.x, v0.y), f2h2(v0.z, v0.w),
                               f2h2(v1.x, v1.y), f2h2(v1.z, v1.w));
            }
        }
        // B chunk: 128 cols x CK k (preconverted half)
        for (int q = tid; q < 128 * (CW / 4); q += 256) {
            int n = q / (CW / 4), u = q % (CW / 4);
            uint4 v = *(const uint4*)(Wt + (size_t)(cb * 128 + n) * KDIM + kc * CK + u * 8);
            *(uint4*)(Bs + n * CS + u * 4) = v;
        }
        __syncthreads();
#pragma unroll
        for (int ks = 0; ks < CK / 16; ks++) {
            const int kb = ks * 8;
            uint32_t a[2][4], b[4][2];
#pragma unroll
            for (int i = 0; i < 2; i++) {
                int row = wm * 32 + i * 16 + grp;
                a[i][0] = As[row * CS + kb + t4];
                a[i][1] = As[(row + 8) * CS + kb + t4];
                a[i][2] = As[row * CS + kb + 4 + t4];
                a[i][3] = As[(row + 8) * CS + kb + 4 + t4];
            }
#pragma unroll
            for (int j = 0; j < 4; j++) {
                int n = wn * 32 + j * 8 + grp;
                b[j][0] = Bs[n * CS + kb + t4];
                b[j][1] = Bs[n * CS + kb + 4 + t4];
            }
#pragma unroll
            for (int i = 0; i < 2; i++)
#pragma unroll
                for (int j = 0; j < 4; j++)
                    mma_f16(acc[i][j], a[i][0], a[i][1], a[i][2], a[i][3], b[j][0], b[j][1]);
        }
    }

    if (!ATTN) {
#pragma unroll
        for (int i = 0; i < 2; i++) {
            int row = rb * 64 + wm * 32 + i * 16 + grp;
#pragma unroll
            for (int j = 0; j < 4; j++) {
                int col = cb * 128 + wn * 32 + j * 8 + 2 * t4;
                int dir = (col >= 384) ? 1 : 0;
                int g = col - dir * 384;
                float b0v = bias[col], b1v = bias[col + 1];
                float2 v0 = make_float2(acc[i][j][0] + b0v, acc[i][j][1] + b1v);
                float2 v1 = make_float2(acc[i][j][2] + b0v, acc[i][j][3] + b1v);
                *(float2*)&out[((size_t)dir * nrows + row) * 384 + g] = v0;
                *(float2*)&out[((size_t)dir * nrows + row + 8) * 384 + g] = v1;
            }
        }
    } else {
        float rsum[2][2];
#pragma unroll
        for (int i = 0; i < 2; i++) { rsum[i][0] = 0.f; rsum[i][1] = 0.f; }
#pragma unroll
        for (int j = 0; j < 4; j++) {
            int col = cb * 128 + wn * 32 + j * 8 + 2 * t4;
            float pv0 = proj[col], pv1 = proj[col + 1];
            float bv0 = bias[col], bv1 = bias[col + 1];
#pragma unroll
            for (int i = 0; i < 2; i++) {
                rsum[i][0] += pv0 * tanhf(acc[i][j][0] + bv0) + pv1 * tanhf(acc[i][j][1] + bv1);
                rsum[i][1] += pv0 * tanhf(acc[i][j][2] + bv0) + pv1 * tanhf(acc[i][j][3] + bv1);
            }
        }
#pragma unroll
        for (int i = 0; i < 2; i++)
#pragma unroll
            for (int sr = 0; sr < 2; sr++) {
                float v = rsum[i][sr];
                v += __shfl_xor_sync(0xffffffffu, v, 1);
                v += __shfl_xor_sync(0xffffffffu, v, 2);
                if (t4 == 0) part_sm[wn][wm * 32 + i * 16 + sr * 8 + grp] = v;
            }
        __syncthreads();
        if (tid < 64)
            out[(size_t)cb * nrows + rb * 64 + tid] =
                part_sm[0][tid] + part_sm[1][tid] + part_sm[2][tid] + part_sm[3][tid];
    }
}

// ========== K3a: intra biGRU, fp16 tensor recurrence, 64 steps ============
// h kept in smem pre-split (hi/lo fp16 packed words + fp32 copy), double-
// buffered -> mainloop is pure LDS+mma; ONE __syncthreads per step.
__global__ __launch_bounds__(256) void k_gru_intra_t(const float* __restrict__ xg,
                                                     const float* __restrict__ Whh,
                                                     const float* __restrict__ bhh,
                                                     float* __restrict__ out) {
    extern __shared__ uint32_t usm[];
    uint32_t* Ws = usm;                        // 384 x 68 words (half2 [n][kw])
    uint32_t* hhb = usm + 384 * 68;            // 2 x (32 x 68) hi words
    uint32_t* hlb = hhb + 2 * 2176;            // 2 x (32 x 68) lo words
    float*    hfb = (float*)(hlb + 2 * 2176);  // 2 x (32 x 132) fp32
    const int bx = blockIdx.x;
    const int dir = bx >> 6, s = (bx >> 1) & 31, bh = bx & 1;
    const int b0 = bh * 32;
    const int tid = threadIdx.x;
    const int lane = tid & 31, w = tid >> 5;
    const int grp = lane >> 2, t4 = lane & 3;

    for (int idx = tid; idx < 384 * 64; idx += 256) {
        int n = idx >> 6, kw = idx & 63;
        const float* p = Whh + dir * 384 * 128 + n * 128 + kw * 2;
        Ws[n * 68 + kw] = f2h2(p[0], p[1]);
    }
    for (int idx = tid; idx < 2176; idx += 256) { hhb[idx] = 0; hlb[idx] = 0; }
    for (int idx = tid; idx < 32 * 132; idx += 256) hfb[idx] = 0.f;
    __syncthreads();

    const int j2 = 16 * w + 2 * t4;
    float br[2][2], bz[2][2], bn[2][2];
#pragma unroll
    for (int jj = 0; jj < 2; jj++)
#pragma unroll
        for (int c = 0; c < 2; c++) {
            int j = j2 + 8 * jj + c;
            br[jj][c] = bhh[dir * 384 + j];
            bz[jj][c] = bhh[dir * 384 + 128 + j];
            bn[jj][c] = bhh[dir * 384 + 256 + j];
        }

    for (int tt = 0; tt < 64; tt++) {
        const int t = dir ? (63 - tt) : tt;
        const int rd = tt & 1, wr = rd ^ 1;
        const uint32_t* hhr = hhb + rd * 2176;
        const uint32_t* hlr = hlb + rd * 2176;
        const float*    hfr = hfb + rd * (32 * 132);
        uint32_t* hhw = hhb + wr * 2176;
        uint32_t* hlw = hlb + wr * 2176;
        float*    hfw = hfb + wr * (32 * 132);

        const float* xgbase = xg + ((size_t)dir * 131072 + ((s * 64 + t) * 64 + b0)) * 384;
        float2 xr[4][2][3];
#pragma unroll
        for (int ri = 0; ri < 4; ri++) {
            const float* p = xgbase + (size_t)(grp + 8 * ri) * 384 + j2;
#pragma unroll
            for (int jj = 0; jj < 2; jj++) {
                xr[ri][jj][0] = *(const float2*)(p + 8 * jj);
                xr[ri][jj][1] = *(const float2*)(p + 128 + 8 * jj);
                xr[ri][jj][2] = *(const float2*)(p + 256 + 8 * jj);
            }
        }

        float acc[2][6][4];
#pragma unroll
        for (int i = 0; i < 2; i++)
#pragma unroll
            for (int nt = 0; nt < 6; nt++)
#pragma unroll
                for (int r = 0; r < 4; r++) acc[i][nt][r] = 0.f;

#pragma unroll
        for (int ks = 0; ks < 8; ks++) {
            const int kb = ks * 8;
            uint32_t ah[2][4], al[2][4];
#pragma unroll
            for (int i = 0; i < 2; i++) {
                int r0 = (16 * i + grp) * 68 + kb + t4;
                int r1 = (16 * i + 8 + grp) * 68 + kb + t4;
                ah[i][0] = hhr[r0]; ah[i][1] = hhr[r1];
                ah[i][2] = hhr[r0 + 4]; ah[i][3] = hhr[r1 + 4];
                al[i][0] = hlr[r0]; al[i][1] = hlr[r1];
                al[i][2] = hlr[r0 + 4]; al[i][3] = hlr[r1 + 4];
            }
#pragma unroll
            for (int nt = 0; nt < 6; nt++) {
                int n = 128 * (nt >> 1) + 16 * w + 8 * (nt & 1) + grp;
                uint32_t brg0 = Ws[n * 68 + kb + t4];
                uint32_t brg1 = Ws[n * 68 + kb + 4 + t4];
                mma_f16(acc[0][nt], ah[0][0], ah[0][1], ah[0][2], ah[0][3], brg0, brg1);
                mma_f16(acc[0][nt], al[0][0], al[0][1], al[0][2], al[0][3], brg0, brg1);
                mma_f16(acc[1][nt], ah[1][0], ah[1][1], ah[1][2], ah[1][3], brg0, brg1);
                mma_f16(acc[1][nt], al[1][0], al[1][1], al[1][2], al[1][3], brg0, brg1);
            }
        }

        // epilogue: thread-local gates; write out + next-buffer h images
#pragma unroll
        for (int i = 0; i < 2; i++)
#pragma unroll
            for (int sr = 0; sr < 2; sr++) {
                int ri = 2 * i + sr;
                int row = 16 * i + 8 * sr + grp;
#pragma unroll
                for (int jj = 0; jj < 2; jj++) {
                    float2 ho = *(const float2*)&hfr[row * 132 + j2 + 8 * jj];
                    float r0 = sigm(xr[ri][jj][0].x + acc[i][jj][2 * sr] + br[jj][0]);
                    float r1 = sigm(xr[ri][jj][0].y + acc[i][jj][2 * sr + 1] + br[jj][1]);
                    float z0 = sigm(xr[ri][jj][1].x + acc[i][2 + jj][2 * sr] + bz[jj][0]);
                    float z1 = sigm(xr[ri][jj][1].y + acc[i][2 + jj][2 * sr + 1] + bz[jj][1]);
                    float n0 = tanhf(xr[ri][jj][2].x + r0 * (acc[i][4 + jj][2 * sr] + bn[jj][0]));
                    float n1 = tanhf(xr[ri][jj][2].y + r1 * (acc[i][4 + jj][2 * sr + 1] + bn[jj][1]));
                    float h0 = (1.f - z0) * n0 + z0 * ho.x;
                    float h1 = (1.f - z1) * n1 + z1 * ho.y;
                    *(float2*)&out[(((size_t)(s * 64 + t)) * 64 + b0 + row) * 256 +
                                   dir * 128 + j2 + 8 * jj] = make_float2(h0, h1);
                    uint32_t hw, lw;
                    split_h2(h0, h1, hw, lw);
                    int wi = row * 68 + 8 * w + t4 + 4 * jj;
                    hhw[wi] = hw;
                    hlw[wi] = lw;
                    *(float2*)&hfw[row * 132 + j2 + 8 * jj] = make_float2(h0, h1);
                }
            }
        __syncthreads();
    }
}

// ---------------- K3b: inter biGRU (small, SIMT) --------------------------
__global__ void k_gru_inter(const float* __restrict__ xg,
                            const float* __restrict__ Whh,
                            const float* __restrict__ bhh,
                            float* __restrict__ out) {
    extern __shared__ float sm[];
    float* Ws = sm;              // 384*133
    float* hs = sm + 384 * 133;  // 2*132
    const int bx = blockIdx.x;
    const int dir = bx >> 5;
    const int b0 = (bx & 31) * 2;
    const int tid = threadIdx.x;
    const int bl = tid >> 7;
    const int j = tid & 127;

    for (int idx = tid; idx < 384 * 128; idx += 256) {
        int row = idx >> 7, k = idx & 127;
        Ws[row * 133 + k] = Whh[dir * 384 * 128 + idx];
    }
    for (int idx = tid; idx < 2 * 132; idx += 256) hs[idx] = 0.f;
    __syncthreads();

    const float br = bhh[dir * 384 + j];
    const float bz = bhh[dir * 384 + 128 + j];
    const float bn = bhh[dir * 384 + 256 + j];

    for (int tt = 0; tt < 32; tt++) {
        const int sstep = dir ? (31 - tt) : tt;
        float ar = 0.f, az = 0.f, an = 0.f;
#pragma unroll 4
        for (int k = 0; k < 128; k++) {
            float hv = hs[bl * 132 + k];
            int ro = j * 133 + k;
            ar = fmaf(hv, Ws[ro], ar);
            az = fmaf(hv, Ws[ro + 128 * 133], az);
            an = fmaf(hv, Ws[ro + 256 * 133], an);
        }
        const int b = b0 + bl;
        const float* xr = xg + (((size_t)dir * 32 + sstep) * 64 + b) * 384;
        float r = sigm(xr[j] + ar + br);
        float z = sigm(xr[128 + j] + az + bz);
        float n = tanhf(xr[256 + j] + r * (an + bn));
        float ho = hs[bl * 132 + j];
        float hv2 = (1.f - z) * n + z * ho;
        out[((size_t)sstep * 64 + b) * 256 + dir * 128 + j] = hv2;
        __syncthreads();
        hs[bl * 132 + j] = hv2;
        __syncthreads();
    }
}

// ------- softmax over t (sums 2 partial planes, writes plane 0) -----------
__global__ void k_softmax_t(float* __restrict__ a) {
    const int NP = S_ * T_ * B_;
    int gid = blockIdx.x * blockDim.x + threadIdx.x;
    if (gid >= S_ * B_) return;
    int s = gid >> 6, b = gid & 63;
    size_t base = (size_t)s * 4096 + b;
    float mx = -1e30f;
    for (int t = 0; t < 64; t++) {
        float v = a[base + t * 64] + a[NP + base + t * 64];
        mx = fmaxf(mx, v);
    }
    float sum = 0.f;
    for (int t = 0; t < 64; t++) {
        float v = a[base + t * 64] + a[NP + base + t * 64];
        sum += expf(v - mx);
    }
    float inv = 1.f / sum;
    for (int t = 0; t < 64; t++) {
        float v = a[base + t * 64] + a[NP + base + t * 64];
        a[base + t * 64] = expf(v - mx) * inv;
    }
}

// ---------------- sentence vectors: sum_t a1 * X ---------------------------
__global__ void k_sent(const float* __restrict__ a1,
                       const float* __restrict__ X,
                       float* __restrict__ sent) {
    const int s = blockIdx.x, bg = blockIdx.y;
    const int h = threadIdx.x;
    float acc[8];
#pragma unroll
    for (int ib = 0; ib < 8; ib++) acc[ib] = 0.f;
    for (int t = 0; t < 64; t++) {
#pragma unroll
        for (int ib = 0; ib < 8; ib++) {
            int b = bg * 8 + ib;
            size_t row = (size_t)s * 4096 + (size_t)t * 64 + b;
            acc[ib] = fmaf(a1[row], X[row * 256 + h], acc[ib]);
        }
    }
#pragma unroll
    for (int ib = 0; ib < 8; ib++)
        sent[((size_t)s * 64 + bg * 8 + ib) * 256 + h] = acc[ib];
}

// --------- doc vector + final linear (sums 2 partial a2 planes) -----------
__global__ void k_doc_final(const float* __restrict__ a2,
                            const float* __restrict__ Xo,
                            const float* __restrict__ Wf,
                            const float* __restrict__ bf,
                            float* __restrict__ outp) {
    __shared__ float red[256];
    const int b = blockIdx.x, h = threadIdx.x;
    float dh = 0.f;
    for (int s2 = 0; s2 < 32; s2++) {
        size_t row = (size_t)s2 * 64 + b;
        float av = a2[row] + a2[S_ * B_ + row];
        dh = fmaf(av, Xo[row * 256 + h], dh);
    }
    for (int c = 0; c < C_; c++) {
        red[h] = dh * Wf[c * 256 + h];
        __syncthreads();
        for (int off = 128; off > 0; off >>= 1) {
            if (h < off) red[h] += red[h + off];
            __syncthreads();
        }
        if (h == 0) outp[b * C_ + c] = red[0] + bf[c];
        __syncthreads();
    }
}

// ---------------- launch ---------------------------------------------------
extern "C" void kernel_launch(void* const* d_in, const int* in_sizes, int n_in,
                              void* d_out, int out_size) {
    const int*   tokens = (const int*)d_in[0];
    const float* embed  = (const float*)d_in[1];
    const float* Wih_a  = (const float*)d_in[2];
    const float* Whh_a  = (const float*)d_in[3];
    const float* bih_a  = (const float*)d_in[4];
    const float* bhh_a  = (const float*)d_in[5];
    const float* WW_a   = (const float*)d_in[6];
    const float* b_a    = (const float*)d_in[7];
    const float* proj_a = (const float*)d_in[8];
    const float* Wih_e  = (const float*)d_in[9];
    const float* Whh_e  = (const float*)d_in[10];
    const float* bih_e  = (const float*)d_in[11];
    const float* bhh_e  = (const float*)d_in[12];
    const float* WW_e   = (const float*)d_in[13];
    const float* b_e    = (const float*)d_in[14];
    const float* proj_e = (const float*)d_in[15];
    const float* Wf     = (const float*)d_in[16];
    const float* bf     = (const float*)d_in[17];
    float* outp = (float*)d_out;

    void *xga_p, *io_p, *a1_p, *sent_p, *xge_p, *ioe_p, *a2_p;
    void *embh_p, *wihA_p, *wihE_p, *ww_p;
    cudaGetSymbolAddress(&xga_p, g_xg_intra);
    cudaGetSymbolAddress(&io_p, g_intra_out);
    cudaGetSymbolAddress(&a1_p, g_a1p);
    cudaGetSymbolAddress(&sent_p, g_sent);
    cudaGetSymbolAddress(&xge_p, g_xg_inter);
    cudaGetSymbolAddress(&ioe_p, g_inter_out);
    cudaGetSymbolAddress(&a2_p, g_a2p);
    cudaGetSymbolAddress(&embh_p, g_emb_h);
    cudaGetSymbolAddress(&wihA_p, g_wihA_h);
    cudaGetSymbolAddress(&wihE_p, g_wihE_h);
    cudaGetSymbolAddress(&ww_p, g_ww_h);

    const int sm_g128  = (64 * 68 + 128 * 68) * 4;               // 52224
    const int sm_g256  = (64 * 36 + 128 * 36) * 4;               // 27648
    const int sm_intra = (384 * 68 + 4 * 2176) * 4 + 2 * 32 * 132 * 4;  // 173056
    const int sm_inter = (384 * 133 + 2 * 132) * 4;
    cudaFuncSetAttribute((const void*)k_gemm4<128, false, true>,
                         cudaFuncAttributeMaxDynamicSharedMemorySize, sm_g128);
    cudaFuncSetAttribute((const void*)k_gemm4<256, false, false>,
                         cudaFuncAttributeMaxDynamicSharedMemorySize, sm_g256);
    cudaFuncSetAttribute((const void*)k_gemm4<256, true, false>,
                         cudaFuncAttributeMaxDynamicSharedMemorySize, sm_g256);
    cudaFuncSetAttribute(k_gru_intra_t, cudaFuncAttributeMaxDynamicSharedMemorySize, sm_intra);
    cudaFuncSetAttribute(k_gru_inter, cudaFuncAttributeMaxDynamicSharedMemorySize, sm_inter);

    // 0) one-time fp16 conversions
    k_prep_h<<<2000, 256>>>(embed, (uint16_t*)embh_p);
    k_prep_h<<<48, 256>>>(Wih_a, (uint16_t*)wihA_p);
    k_prep_h<<<96, 256>>>(Wih_e, (uint16_t*)wihE_p);
    k_prep_ww_h<<<dim3(256, 2), 256>>>(WW_a, WW_e, (uint16_t*)ww_p);
    // 1) intra input gates: gathered fp16 GEMM (full-K resident), rows = 131072
    k_gemm4<128, false, true><<<dim3(2048, 6), 256, sm_g128>>>(
        tokens, (uint16_t*)embh_p, (uint16_t*)wihA_p, bih_a, nullptr,
        (float*)xga_p, 131072);
    // 2) intra biGRU (fp16 tensor recurrence, pre-split h, 1 barrier/step)
    k_gru_intra_t<<<128, 256, sm_intra>>>((float*)xga_p, Whh_a, bhh_a, (float*)io_p);
    // 3) word attention partial logits (2 column-halves -> 2 planes)
    k_gemm4<256, true, false><<<dim3(2048, 2), 256, sm_g256>>>(
        nullptr, (float*)io_p, (uint16_t*)ww_p, b_a, proj_a, (float*)a1_p, 131072);
    // 4) softmax over tokens (sums planes)
    k_softmax_t<<<8, 256>>>((float*)a1_p);
    // 5) sentence vectors
    k_sent<<<dim3(32, 8), 256>>>((float*)a1_p, (float*)io_p, (float*)sent_p);
    // 6) inter input gates: rows = 2048
    k_gemm4<256, false, false><<<dim3(32, 6), 256, sm_g256>>>(
        nullptr, (float*)sent_p, (uint16_t*)wihE_p, bih_e, nullptr,
        (float*)xge_p, 2048);
    // 7) inter biGRU
    k_gru_inter<<<64, 256, sm_inter>>>((float*)xge_p, Whh_e, bhh_e, (float*)ioe_p);
    // 8) sentence attention partial logits (NO softmax)
    k_gemm4<256, true, false><<<dim3(32, 2), 256, sm_g256>>>(
        nullptr, (float*)ioe_p, (uint16_t*)ww_p + 65536, b_e, proj_e, (float*)a2_p, 2048);
    // 9) doc vector + final linear
    k_doc_final<<<64, 256>>>((float*)a2_p, (float*)ioe_p, Wf, bf, outp);
}

// round 12
// speedup vs baseline: 1.4549x; 1.4549x over previous
#include <cuda_runtime.h>
#include <cuda_fp16.h>
#include <math.h>
#include <stdint.h>

#define S_  32
#define T_  64
#define B_  64
#define C_  5
#define VOCAB_ 32000

// ---------------- scratch (device globals; no allocation) ----------------
__device__ float g_xg_intra[(size_t)2*S_*T_*B_*384]; // [dir][row(s,t,b)][384]
__device__ float g_intra_out[(size_t)S_*T_*B_*256];  // [s][t][b][256] fwd|bwd
__device__ float g_a1p[2*S_*T_*B_];                  // 2 partial planes
__device__ float g_sent[S_*B_*256];
__device__ float g_xg_inter[2*S_*B_*384];
__device__ float g_inter_out[S_*B_*256];
__device__ float g_a2p[2*S_*B_];
// fp16 preconversions
__device__ uint16_t g_emb_h[(size_t)VOCAB_*128];     // embed table half
__device__ uint16_t g_wihA_h[768*128];               // Wih_a half [col][k]
__device__ uint16_t g_wihE_h[768*256];               // Wih_e half [col][k]
__device__ uint16_t g_ww_h[2*256*256];               // WW_a/WW_e transposed half [n][k]

__device__ __forceinline__ float sigm(float x) { return 1.f / (1.f + expf(-x)); }

__device__ __forceinline__ uint32_t f2h2(float x, float y) {
    __half2 h = __floats2half2_rn(x, y);
    return *(uint32_t*)&h;
}

__device__ __forceinline__ void mma_f16(float c[4],
                                        uint32_t a0, uint32_t a1, uint32_t a2, uint32_t a3,
                                        uint32_t b0, uint32_t b1) {
    asm volatile(
        "mma.sync.aligned.m16n8k16.row.col.f32.f16.f16.f32 "
        "{%0,%1,%2,%3}, {%4,%5,%6,%7}, {%8,%9}, {%0,%1,%2,%3};"
        : "+f"(c[0]), "+f"(c[1]), "+f"(c[2]), "+f"(c[3])
        : "r"(a0), "r"(a1), "r"(a2), "r"(a3), "r"(b0), "r"(b1));
}

// ---- prep kernels: one-time fp16 conversions ------------------------------
__global__ void k_prep_h(const float* __restrict__ in, uint16_t* __restrict__ out) {
    size_t q = ((size_t)blockIdx.x * 256 + threadIdx.x) * 8;
    float4 v0 = *(const float4*)(in + q);
    float4 v1 = *(const float4*)(in + q + 4);
    uint4 u = make_uint4(f2h2(v0.x, v0.y), f2h2(v0.z, v0.w),
                         f2h2(v1.x, v1.y), f2h2(v1.z, v1.w));
    *(uint4*)(out + q) = u;
}
__global__ void k_prep_ww_h(const float* __restrict__ Wa, const float* __restrict__ We,
                            uint16_t* __restrict__ out) {
    int idx = blockIdx.x * 256 + threadIdx.x;       // 0..65535
    const float* W = blockIdx.y ? We : Wa;
    int n = idx >> 8, h = idx & 255;
    __half v = __float2half_rn(W[h * 256 + n]);
    out[blockIdx.y * 65536 + n * 256 + h] = *(uint16_t*)&v;
}

// ============ unified fp16 tensor GEMM: 64x128 tiles, 3 blocks/SM =========
// C[row, col] = sum_k A[row,k] * W[col,k]   (W preconverted half [col][k])
template<int KDIM, bool ATTN, bool AHALF>
__global__ __launch_bounds__(256, 3) void k_gemm4(const int* __restrict__ tokens,
                                                  const void* __restrict__ Av,
                                                  const uint16_t* __restrict__ Wt,
                                                  const float* __restrict__ bias,
                                                  const float* __restrict__ proj,
                                                  float* __restrict__ out,
                                                  int nrows) {
    extern __shared__ uint32_t usm[];
    uint32_t* As = usm;              // 64 rows x 36 words (64-k chunk as half2)
    uint32_t* Bs = usm + 64 * 36;    // 128 cols x 36 words
    __shared__ int toks[64];
    __shared__ float part_sm[4][65];
    const int rb = blockIdx.x, cb = blockIdx.y;
    const int tid = threadIdx.x;
    const int lane = tid & 31, wid = tid >> 5;
    const int wm = wid >> 2, wn = wid & 3;   // 2 (M) x 4 (N)
    const int grp = lane >> 2, t4 = lane & 3;

    if (tokens) {
        if (tid < 64) toks[tid] = tokens[rb * 64 + tid];
        __syncthreads();
    }

    float acc[2][4][4];
#pragma unroll
    for (int i = 0; i < 2; i++)
#pragma unroll
        for (int j = 0; j < 4; j++)
#pragma unroll
            for (int r = 0; r < 4; r++) acc[i][j][r] = 0.f;

#pragma unroll
    for (int kc = 0; kc < KDIM / 64; kc++) {
        if (kc) __syncthreads();
        // A chunk: 64 rows x 64 k (8 halves per uint4)
        for (int q = tid; q < 64 * 8; q += 256) {
            int r = q >> 3, u = q & 7;
            size_t rowbase = tokens ? (size_t)toks[r] * KDIM
                                    : (size_t)(rb * 64 + r) * KDIM;
            if (AHALF) {
                uint4 v = *(const uint4*)((const uint16_t*)Av + rowbase + kc * 64 + u * 8);
                *(uint4*)(As + r * 36 + u * 4) = v;
            } else {
                const float* src = (const float*)Av + rowbase + kc * 64 + u * 8;
                float4 v0 = *(const float4*)src;
                float4 v1 = *(const float4*)(src + 4);
                *(uint4*)(As + r * 36 + u * 4) =
                    make_uint4(f2h2(v0.x, v0.y), f2h2(v0.z, v0.w),
                               f2h2(v1.x, v1.y), f2h2(v1.z, v1.w));
            }
        }
        // B chunk: 128 cols x 64 k (preconverted half)
        for (int q = tid; q < 128 * 8; q += 256) {
            int n = q >> 3, u = q & 7;
            uint4 v = *(const uint4*)(Wt + (size_t)(cb * 128 + n) * KDIM + kc * 64 + u * 8);
            *(uint4*)(Bs + n * 36 + u * 4) = v;
        }
        __syncthreads();
#pragma unroll
        for (int ks = 0; ks < 4; ks++) {          // 4 x k16 per 64-k chunk
            const int kb = ks * 8;
            uint32_t a[2][4], b[4][2];
#pragma unroll
            for (int i = 0; i < 2; i++) {
                int row = wm * 32 + i * 16 + grp;
                a[i][0] = As[row * 36 + kb + t4];
                a[i][1] = As[(row + 8) * 36 + kb + t4];
                a[i][2] = As[row * 36 + kb + 4 + t4];
                a[i][3] = As[(row + 8) * 36 + kb + 4 + t4];
            }
#pragma unroll
            for (int j = 0; j < 4; j++) {
                int n = wn * 32 + j * 8 + grp;
                b[j][0] = Bs[n * 36 + kb + t4];
                b[j][1] = Bs[n * 36 + kb + 4 + t4];
            }
#pragma unroll
            for (int i = 0; i < 2; i++)
#pragma unroll
                for (int j = 0; j < 4; j++)
                    mma_f16(acc[i][j], a[i][0], a[i][1], a[i][2], a[i][3], b[j][0], b[j][1]);
        }
    }

    if (!ATTN) {
#pragma unroll
        for (int i = 0; i < 2; i++) {
            int row = rb * 64 + wm * 32 + i * 16 + grp;
#pragma unroll
            for (int j = 0; j < 4; j++) {
                int col = cb * 128 + wn * 32 + j * 8 + 2 * t4;
                int dir = (col >= 384) ? 1 : 0;
                int g = col - dir * 384;
                float b0v = bias[col], b1v = bias[col + 1];
                float2 v0 = make_float2(acc[i][j][0] + b0v, acc[i][j][1] + b1v);
                float2 v1 = make_float2(acc[i][j][2] + b0v, acc[i][j][3] + b1v);
                *(float2*)&out[((size_t)dir * nrows + row) * 384 + g] = v0;
                *(float2*)&out[((size_t)dir * nrows + row + 8) * 384 + g] = v1;
            }
        }
    } else {
        float rsum[2][2];
#pragma unroll
        for (int i = 0; i < 2; i++) { rsum[i][0] = 0.f; rsum[i][1] = 0.f; }
#pragma unroll
        for (int j = 0; j < 4; j++) {
            int col = cb * 128 + wn * 32 + j * 8 + 2 * t4;
            float pv0 = proj[col], pv1 = proj[col + 1];
            float bv0 = bias[col], bv1 = bias[col + 1];
#pragma unroll
            for (int i = 0; i < 2; i++) {
                rsum[i][0] += pv0 * tanhf(acc[i][j][0] + bv0) + pv1 * tanhf(acc[i][j][1] + bv1);
                rsum[i][1] += pv0 * tanhf(acc[i][j][2] + bv0) + pv1 * tanhf(acc[i][j][3] + bv1);
            }
        }
#pragma unroll
        for (int i = 0; i < 2; i++)
#pragma unroll
            for (int sr = 0; sr < 2; sr++) {
                float v = rsum[i][sr];
                v += __shfl_xor_sync(0xffffffffu, v, 1);
                v += __shfl_xor_sync(0xffffffffu, v, 2);
                if (t4 == 0) part_sm[wn][wm * 32 + i * 16 + sr * 8 + grp] = v;
            }
        __syncthreads();
        if (tid < 64)
            out[(size_t)cb * nrows + rb * 64 + tid] =
                part_sm[0][tid] + part_sm[1][tid] + part_sm[2][tid] + part_sm[3][tid];
    }
}

// ========== K3a: intra biGRU, fp16 tensor recurrence, 64 steps ============
// R10 structure exactly; single change: 1-term fp16 h (12 mma/ks, was 24).
__global__ __launch_bounds__(256) void k_gru_intra_t(const float* __restrict__ xg,
                                                     const float* __restrict__ Whh,
                                                     const float* __restrict__ bhh,
                                                     float* __restrict__ out) {
    extern __shared__ uint32_t usm[];
    uint32_t* Ws = usm;                       // 384 x 68 words (half2 [n][kw])
    float* hsm = (float*)(usm + 384 * 68);    // 32 x 132 fp32
    const int bx = blockIdx.x;
    const int dir = bx >> 6, s = (bx >> 1) & 31, bh = bx & 1;
    const int b0 = bh * 32;
    const int tid = threadIdx.x;
    const int lane = tid & 31, w = tid >> 5;
    const int grp = lane >> 2, t4 = lane & 3;

    for (int idx = tid; idx < 384 * 64; idx += 256) {
        int n = idx >> 6, kw = idx & 63;
        const float* p = Whh + dir * 384 * 128 + n * 128 + kw * 2;
        Ws[n * 68 + kw] = f2h2(p[0], p[1]);
    }
    for (int idx = tid; idx < 32 * 132; idx += 256) hsm[idx] = 0.f;
    __syncthreads();

    const int j2 = 16 * w + 2 * t4;
    float br[2][2], bz[2][2], bn[2][2];
#pragma unroll
    for (int jj = 0; jj < 2; jj++)
#pragma unroll
        for (int c = 0; c < 2; c++) {
            int j = j2 + 8 * jj + c;
            br[jj][c] = bhh[dir * 384 + j];
            bz[jj][c] = bhh[dir * 384 + 128 + j];
            bn[jj][c] = bhh[dir * 384 + 256 + j];
        }

    for (int tt = 0; tt < 64; tt++) {
        const int t = dir ? (63 - tt) : tt;
        const float* xgbase = xg + ((size_t)dir * 131072 + ((s * 64 + t) * 64 + b0)) * 384;

        float2 xr[4][2][3];
#pragma unroll
        for (int ri = 0; ri < 4; ri++) {
            const float* p = xgbase + (size_t)(grp + 8 * ri) * 384 + j2;
#pragma unroll
            for (int jj = 0; jj < 2; jj++) {
                xr[ri][jj][0] = *(const float2*)(p + 8 * jj);
                xr[ri][jj][1] = *(const float2*)(p + 128 + 8 * jj);
                xr[ri][jj][2] = *(const float2*)(p + 256 + 8 * jj);
            }
        }

        float acc[2][6][4];
#pragma unroll
        for (int i = 0; i < 2; i++)
#pragma unroll
            for (int nt = 0; nt < 6; nt++)
#pragma unroll
                for (int r = 0; r < 4; r++) acc[i][nt][r] = 0.f;

#pragma unroll
        for (int ks = 0; ks < 8; ks++) {          // 8 x k16 over K=128
            uint32_t ah[2][4];
#pragma unroll
            for (int i = 0; i < 2; i++) {
                float2 p0 = *(const float2*)&hsm[(16 * i + grp) * 132 + 16 * ks + 2 * t4];
                float2 p1 = *(const float2*)&hsm[(16 * i + 8 + grp) * 132 + 16 * ks + 2 * t4];
                float2 p2 = *(const float2*)&hsm[(16 * i + grp) * 132 + 16 * ks + 8 + 2 * t4];
                float2 p3 = *(const float2*)&hsm[(16 * i + 8 + grp) * 132 + 16 * ks + 8 + 2 * t4];
                ah[i][0] = f2h2(p0.x, p0.y);
                ah[i][1] = f2h2(p1.x, p1.y);
                ah[i][2] = f2h2(p2.x, p2.y);
                ah[i][3] = f2h2(p3.x, p3.y);
            }
            const int kb = ks * 8;
#pragma unroll
            for (int nt = 0; nt < 6; nt++) {
                int n = 128 * (nt >> 1) + 16 * w + 8 * (nt & 1) + grp;
                uint32_t brg0 = Ws[n * 68 + kb + t4];
                uint32_t brg1 = Ws[n * 68 + kb + 4 + t4];
                mma_f16(acc[0][nt], ah[0][0], ah[0][1], ah[0][2], ah[0][3], brg0, brg1);
                mma_f16(acc[1][nt], ah[1][0], ah[1][1], ah[1][2], ah[1][3], brg0, brg1);
            }
        }

        float hn[2][2][2][2];
#pragma unroll
        for (int i = 0; i < 2; i++)
#pragma unroll
            for (int sr = 0; sr < 2; sr++) {
                int ri = 2 * i + sr;
                int row = 16 * i + 8 * sr + grp;
#pragma unroll
                for (int jj = 0; jj < 2; jj++) {
                    float2 ho = *(const float2*)&hsm[row * 132 + j2 + 8 * jj];
                    float r0 = sigm(xr[ri][jj][0].x + acc[i][jj][2 * sr] + br[jj][0]);
                    float r1 = sigm(xr[ri][jj][0].y + acc[i][jj][2 * sr + 1] + br[jj][1]);
                    float z0 = sigm(xr[ri][jj][1].x + acc[i][2 + jj][2 * sr] + bz[jj][0]);
                    float z1 = sigm(xr[ri][jj][1].y + acc[i][2 + jj][2 * sr + 1] + bz[jj][1]);
                    float n0 = tanhf(xr[ri][jj][2].x + r0 * (acc[i][4 + jj][2 * sr] + bn[jj][0]));
                    float n1 = tanhf(xr[ri][jj][2].y + r1 * (acc[i][4 + jj][2 * sr + 1] + bn[jj][1]));
                    float h0 = (1.f - z0) * n0 + z0 * ho.x;
                    float h1 = (1.f - z1) * n1 + z1 * ho.y;
                    hn[i][sr][jj][0] = h0;
                    hn[i][sr][jj][1] = h1;
                    *(float2*)&out[(((size_t)(s * 64 + t)) * 64 + b0 + row) * 256 +
                                   dir * 128 + j2 + 8 * jj] = make_float2(h0, h1);
                }
            }
        __syncthreads();
#pragma unroll
        for (int i = 0; i < 2; i++)
#pragma unroll
            for (int sr = 0; sr < 2; sr++) {
                int row = 16 * i + 8 * sr + grp;
#pragma unroll
                for (int jj = 0; jj < 2; jj++)
                    *(float2*)&hsm[row * 132 + j2 + 8 * jj] =
                        make_float2(hn[i][sr][jj][0], hn[i][sr][jj][1]);
            }
        __syncthreads();
    }
}

// ---------------- K3b: inter biGRU (small, SIMT) --------------------------
__global__ void k_gru_inter(const float* __restrict__ xg,
                            const float* __restrict__ Whh,
                            const float* __restrict__ bhh,
                            float* __restrict__ out) {
    extern __shared__ float sm[];
    float* Ws = sm;              // 384*133
    float* hs = sm + 384 * 133;  // 2*132
    const int bx = blockIdx.x;
    const int dir = bx >> 5;
    const int b0 = (bx & 31) * 2;
    const int tid = threadIdx.x;
    const int bl = tid >> 7;
    const int j = tid & 127;

    for (int idx = tid; idx < 384 * 128; idx += 256) {
        int row = idx >> 7, k = idx & 127;
        Ws[row * 133 + k] = Whh[dir * 384 * 128 + idx];
    }
    for (int idx = tid; idx < 2 * 132; idx += 256) hs[idx] = 0.f;
    __syncthreads();

    const float br = bhh[dir * 384 + j];
    const float bz = bhh[dir * 384 + 128 + j];
    const float bn = bhh[dir * 384 + 256 + j];

    for (int tt = 0; tt < 32; tt++) {
        const int sstep = dir ? (31 - tt) : tt;
        float ar = 0.f, az = 0.f, an = 0.f;
#pragma unroll 4
        for (int k = 0; k < 128; k++) {
            float hv = hs[bl * 132 + k];
            int ro = j * 133 + k;
            ar = fmaf(hv, Ws[ro], ar);
            az = fmaf(hv, Ws[ro + 128 * 133], az);
            an = fmaf(hv, Ws[ro + 256 * 133], an);
        }
        const int b = b0 + bl;
        const float* xr = xg + (((size_t)dir * 32 + sstep) * 64 + b) * 384;
        float r = sigm(xr[j] + ar + br);
        float z = sigm(xr[128 + j] + az + bz);
        float n = tanhf(xr[256 + j] + r * (an + bn));
        float ho = hs[bl * 132 + j];
        float hv2 = (1.f - z) * n + z * ho;
        out[((size_t)sstep * 64 + b) * 256 + dir * 128 + j] = hv2;
        __syncthreads();
        hs[bl * 132 + j] = hv2;
        __syncthreads();
    }
}

// ------- softmax over t (sums 2 partial planes, writes plane 0) -----------
__global__ void k_softmax_t(float* __restrict__ a) {
    const int NP = S_ * T_ * B_;
    int gid = blockIdx.x * blockDim.x + threadIdx.x;
    if (gid >= S_ * B_) return;
    int s = gid >> 6, b = gid & 63;
    size_t base = (size_t)s * 4096 + b;
    float mx = -1e30f;
    for (int t = 0; t < 64; t++) {
        float v = a[base + t * 64] + a[NP + base + t * 64];
        mx = fmaxf(mx, v);
    }
    float sum = 0.f;
    for (int t = 0; t < 64; t++) {
        float v = a[base + t * 64] + a[NP + base + t * 64];
        sum += expf(v - mx);
    }
    float inv = 1.f / sum;
    for (int t = 0; t < 64; t++) {
        float v = a[base + t * 64] + a[NP + base + t * 64];
        a[base + t * 64] = expf(v - mx) * inv;
    }
}

// ---------------- sentence vectors: sum_t a1 * X ---------------------------
__global__ void k_sent(const float* __restrict__ a1,
                       const float* __restrict__ X,
                       float* __restrict__ sent) {
    const int s = blockIdx.x, bg = blockIdx.y;
    const int h = threadIdx.x;
    float acc[8];
#pragma unroll
    for (int ib = 0; ib < 8; ib++) acc[ib] = 0.f;
    for (int t = 0; t < 64; t++) {
#pragma unroll
        for (int ib = 0; ib < 8; ib++) {
            int b = bg * 8 + ib;
            size_t row = (size_t)s * 4096 + (size_t)t * 64 + b;
            acc[ib] = fmaf(a1[row], X[row * 256 + h], acc[ib]);
        }
    }
#pragma unroll
    for (int ib = 0; ib < 8; ib++)
        sent[((size_t)s * 64 + bg * 8 + ib) * 256 + h] = acc[ib];
}

// --------- doc vector + final linear (sums 2 partial a2 planes) -----------
__global__ void k_doc_final(const float* __restrict__ a2,
                            const float* __restrict__ Xo,
                            const float* __restrict__ Wf,
                            const float* __restrict__ bf,
                            float* __restrict__ outp) {
    __shared__ float red[256];
    const int b = blockIdx.x, h = threadIdx.x;
    float dh = 0.f;
    for (int s2 = 0; s2 < 32; s2++) {
        size_t row = (size_t)s2 * 64 + b;
        float av = a2[row] + a2[S_ * B_ + row];
        dh = fmaf(av, Xo[row * 256 + h], dh);
    }
    for (int c = 0; c < C_; c++) {
        red[h] = dh * Wf[c * 256 + h];
        __syncthreads();
        for (int off = 128; off > 0; off >>= 1) {
            if (h < off) red[h] += red[h + off];
            __syncthreads();
        }
        if (h == 0) outp[b * C_ + c] = red[0] + bf[c];
        __syncthreads();
    }
}

// ---------------- launch ---------------------------------------------------
extern "C" void kernel_launch(void* const* d_in, const int* in_sizes, int n_in,
                              void* d_out, int out_size) {
    const int*   tokens = (const int*)d_in[0];
    const float* embed  = (const float*)d_in[1];
    const float* Wih_a  = (const float*)d_in[2];
    const float* Whh_a  = (const float*)d_in[3];
    const float* bih_a  = (const float*)d_in[4];
    const float* bhh_a  = (const float*)d_in[5];
    const float* WW_a   = (const float*)d_in[6];
    const float* b_a    = (const float*)d_in[7];
    const float* proj_a = (const float*)d_in[8];
    const float* Wih_e  = (const float*)d_in[9];
    const float* Whh_e  = (const float*)d_in[10];
    const float* bih_e  = (const float*)d_in[11];
    const float* bhh_e  = (const float*)d_in[12];
    const float* WW_e   = (const float*)d_in[13];
    const float* b_e    = (const float*)d_in[14];
    const float* proj_e = (const float*)d_in[15];
    const float* Wf     = (const float*)d_in[16];
    const float* bf     = (const float*)d_in[17];
    float* outp = (float*)d_out;

    void *xga_p, *io_p, *a1_p, *sent_p, *xge_p, *ioe_p, *a2_p;
    void *embh_p, *wihA_p, *wihE_p, *ww_p;
    cudaGetSymbolAddress(&xga_p, g_xg_intra);
    cudaGetSymbolAddress(&io_p, g_intra_out);
    cudaGetSymbolAddress(&a1_p, g_a1p);
    cudaGetSymbolAddress(&sent_p, g_sent);
    cudaGetSymbolAddress(&xge_p, g_xg_inter);
    cudaGetSymbolAddress(&ioe_p, g_inter_out);
    cudaGetSymbolAddress(&a2_p, g_a2p);
    cudaGetSymbolAddress(&embh_p, g_emb_h);
    cudaGetSymbolAddress(&wihA_p, g_wihA_h);
    cudaGetSymbolAddress(&wihE_p, g_wihE_h);
    cudaGetSymbolAddress(&ww_p, g_ww_h);

    const int sm_gemm  = (64 * 36 + 128 * 36) * 4;    // 27648
    const int sm_intra = (384 * 68 + 32 * 132) * 4;   // 121344
    const int sm_inter = (384 * 133 + 2 * 132) * 4;
    cudaFuncSetAttribute((const void*)k_gemm4<128, false, true>,
                         cudaFuncAttributeMaxDynamicSharedMemorySize, sm_gemm);
    cudaFuncSetAttribute((const void*)k_gemm4<256, false, false>,
                         cudaFuncAttributeMaxDynamicSharedMemorySize, sm_gemm);
    cudaFuncSetAttribute((const void*)k_gemm4<256, true, false>,
                         cudaFuncAttributeMaxDynamicSharedMemorySize, sm_gemm);
    cudaFuncSetAttribute(k_gru_intra_t, cudaFuncAttributeMaxDynamicSharedMemorySize, sm_intra);
    cudaFuncSetAttribute(k_gru_inter, cudaFuncAttributeMaxDynamicSharedMemorySize, sm_inter);

    // 0) one-time fp16 conversions
    k_prep_h<<<2000, 256>>>(embed, (uint16_t*)embh_p);
    k_prep_h<<<48, 256>>>(Wih_a, (uint16_t*)wihA_p);
    k_prep_h<<<96, 256>>>(Wih_e, (uint16_t*)wihE_p);
    k_prep_ww_h<<<dim3(256, 2), 256>>>(WW_a, WW_e, (uint16_t*)ww_p);
    // 1) intra input gates: gathered fp16 GEMM, rows = 131072
    k_gemm4<128, false, true><<<dim3(2048, 6), 256, sm_gemm>>>(
        tokens, (uint16_t*)embh_p, (uint16_t*)wihA_p, bih_a, nullptr,
        (float*)xga_p, 131072);
    // 2) intra biGRU (fp16 tensor recurrence, 1-term h)
    k_gru_intra_t<<<128, 256, sm_intra>>>((float*)xga_p, Whh_a, bhh_a, (float*)io_p);
    // 3) word attention partial logits (2 column-halves -> 2 planes)
    k_gemm4<256, true, false><<<dim3(2048, 2), 256, sm_gemm>>>(
        nullptr, (float*)io_p, (uint16_t*)ww_p, b_a, proj_a, (float*)a1_p, 131072);
    // 4) softmax over tokens (sums planes)
    k_softmax_t<<<8, 256>>>((float*)a1_p);
    // 5) sentence vectors
    k_sent<<<dim3(32, 8), 256>>>((float*)a1_p, (float*)io_p, (float*)sent_p);
    // 6) inter input gates: rows = 2048
    k_gemm4<256, false, false><<<dim3(32, 6), 256, sm_gemm>>>(
        nullptr, (float*)sent_p, (uint16_t*)wihE_p, bih_e, nullptr,
        (float*)xge_p, 2048);
    // 7) inter biGRU
    k_gru_inter<<<64, 256, sm_inter>>>((float*)xge_p, Whh_e, bhh_e, (float*)ioe_p);
    // 8) sentence attention partial logits (NO softmax)
    k_gemm4<256, true, false><<<dim3(32, 2), 256, sm_gemm>>>(
        nullptr, (float*)ioe_p, (uint16_t*)ww_p + 65536, b_e, proj_e, (float*)a2_p, 2048);
    // 9) doc vector + final linear
    k_doc_final<<<64, 256>>>((float*)a2_p, (float*)ioe_p, Wf, bf, outp);
}

// round 13
// speedup vs baseline: 1.5404x; 1.0587x over previous
#include <cuda_runtime.h>
#include <cuda_fp16.h>
#include <math.h>
#include <stdint.h>

#define S_  32
#define T_  64
#define B_  64
#define C_  5
#define VOCAB_ 32000

// ---------------- scratch (device globals; no allocation) ----------------
__device__ uint16_t g_xg_h[(size_t)2*S_*T_*B_*384]; // fp16 [dir][row(s,t,b)][384]
__device__ uint16_t g_io_h[(size_t)S_*T_*B_*256];   // fp16 [s][t][b][256] fwd|bwd
__device__ float g_a1p[2*S_*T_*B_];                 // 2 partial planes
__device__ float g_sent[S_*B_*256];
__device__ float g_xg_inter[2*S_*B_*384];
__device__ float g_inter_out[S_*B_*256];
__device__ float g_a2p[2*S_*B_];
// fp16 preconversions
__device__ uint16_t g_emb_h[(size_t)VOCAB_*128];    // embed table half
__device__ uint16_t g_wihA_h[768*128];              // Wih_a half [col][k]
__device__ uint16_t g_wihE_h[768*256];              // Wih_e half [col][k]
__device__ uint16_t g_ww_h[2*256*256];              // WW_a/WW_e transposed half [n][k]

__device__ __forceinline__ float sigm(float x) { return 1.f / (1.f + expf(-x)); }

__device__ __forceinline__ uint32_t f2h2(float x, float y) {
    __half2 h = __floats2half2_rn(x, y);
    return *(uint32_t*)&h;
}
__device__ __forceinline__ float2 h2f2(uint32_t u) {
    return __half22float2(*(__half2*)&u);
}

__device__ __forceinline__ void mma_f16(float c[4],
                                        uint32_t a0, uint32_t a1, uint32_t a2, uint32_t a3,
                                        uint32_t b0, uint32_t b1) {
    asm volatile(
        "mma.sync.aligned.m16n8k16.row.col.f32.f16.f16.f32 "
        "{%0,%1,%2,%3}, {%4,%5,%6,%7}, {%8,%9}, {%0,%1,%2,%3};"
        : "+f"(c[0]), "+f"(c[1]), "+f"(c[2]), "+f"(c[3])
        : "r"(a0), "r"(a1), "r"(a2), "r"(a3), "r"(b0), "r"(b1));
}

// ---- prep kernels: one-time fp16 conversions ------------------------------
__global__ void k_prep_h(const float* __restrict__ in, uint16_t* __restrict__ out) {
    size_t q = ((size_t)blockIdx.x * 256 + threadIdx.x) * 8;
    float4 v0 = *(const float4*)(in + q);
    float4 v1 = *(const float4*)(in + q + 4);
    uint4 u = make_uint4(f2h2(v0.x, v0.y), f2h2(v0.z, v0.w),
                         f2h2(v1.x, v1.y), f2h2(v1.z, v1.w));
    *(uint4*)(out + q) = u;
}
__global__ void k_prep_ww_h(const float* __restrict__ Wa, const float* __restrict__ We,
                            uint16_t* __restrict__ out) {
    int idx = blockIdx.x * 256 + threadIdx.x;       // 0..65535
    const float* W = blockIdx.y ? We : Wa;
    int n = idx >> 8, h = idx & 255;
    __half v = __float2half_rn(W[h * 256 + n]);
    out[blockIdx.y * 65536 + n * 256 + h] = *(uint16_t*)&v;
}

// ============ unified fp16 tensor GEMM: 64x128 tiles, 3 blocks/SM =========
// C[row, col] = sum_k A[row,k] * W[col,k]   (W preconverted half [col][k])
// OH: gate output stored as fp16 (half2 packed) instead of fp32.
template<int KDIM, bool ATTN, bool AHALF, bool OH>
__global__ __launch_bounds__(256, 3) void k_gemm4(const int* __restrict__ tokens,
                                                  const void* __restrict__ Av,
                                                  const uint16_t* __restrict__ Wt,
                                                  const float* __restrict__ bias,
                                                  const float* __restrict__ proj,
                                                  void* __restrict__ outv,
                                                  int nrows) {
    extern __shared__ uint32_t usm[];
    uint32_t* As = usm;              // 64 rows x 36 words (64-k chunk as half2)
    uint32_t* Bs = usm + 64 * 36;    // 128 cols x 36 words
    __shared__ int toks[64];
    __shared__ float part_sm[4][65];
    const int rb = blockIdx.x, cb = blockIdx.y;
    const int tid = threadIdx.x;
    const int lane = tid & 31, wid = tid >> 5;
    const int wm = wid >> 2, wn = wid & 3;   // 2 (M) x 4 (N)
    const int grp = lane >> 2, t4 = lane & 3;

    if (tokens) {
        if (tid < 64) toks[tid] = tokens[rb * 64 + tid];
        __syncthreads();
    }

    float acc[2][4][4];
#pragma unroll
    for (int i = 0; i < 2; i++)
#pragma unroll
        for (int j = 0; j < 4; j++)
#pragma unroll
            for (int r = 0; r < 4; r++) acc[i][j][r] = 0.f;

#pragma unroll
    for (int kc = 0; kc < KDIM / 64; kc++) {
        if (kc) __syncthreads();
        // A chunk: 64 rows x 64 k (8 halves per uint4)
        for (int q = tid; q < 64 * 8; q += 256) {
            int r = q >> 3, u = q & 7;
            size_t rowbase = tokens ? (size_t)toks[r] * KDIM
                                    : (size_t)(rb * 64 + r) * KDIM;
            if (AHALF) {
                uint4 v = *(const uint4*)((const uint16_t*)Av + rowbase + kc * 64 + u * 8);
                *(uint4*)(As + r * 36 + u * 4) = v;
            } else {
                const float* src = (const float*)Av + rowbase + kc * 64 + u * 8;
                float4 v0 = *(const float4*)src;
                float4 v1 = *(const float4*)(src + 4);
                *(uint4*)(As + r * 36 + u * 4) =
                    make_uint4(f2h2(v0.x, v0.y), f2h2(v0.z, v0.w),
                               f2h2(v1.x, v1.y), f2h2(v1.z, v1.w));
            }
        }
        // B chunk: 128 cols x 64 k (preconverted half)
        for (int q = tid; q < 128 * 8; q += 256) {
            int n = q >> 3, u = q & 7;
            uint4 v = *(const uint4*)(Wt + (size_t)(cb * 128 + n) * KDIM + kc * 64 + u * 8);
            *(uint4*)(Bs + n * 36 + u * 4) = v;
        }
        __syncthreads();
#pragma unroll
        for (int ks = 0; ks < 4; ks++) {          // 4 x k16 per 64-k chunk
            const int kb = ks * 8;
            uint32_t a[2][4], b[4][2];
#pragma unroll
            for (int i = 0; i < 2; i++) {
                int row = wm * 32 + i * 16 + grp;
                a[i][0] = As[row * 36 + kb + t4];
                a[i][1] = As[(row + 8) * 36 + kb + t4];
                a[i][2] = As[row * 36 + kb + 4 + t4];
                a[i][3] = As[(row + 8) * 36 + kb + 4 + t4];
            }
#pragma unroll
            for (int j = 0; j < 4; j++) {
                int n = wn * 32 + j * 8 + grp;
                b[j][0] = Bs[n * 36 + kb + t4];
                b[j][1] = Bs[n * 36 + kb + 4 + t4];
            }
#pragma unroll
            for (int i = 0; i < 2; i++)
#pragma unroll
                for (int j = 0; j < 4; j++)
                    mma_f16(acc[i][j], a[i][0], a[i][1], a[i][2], a[i][3], b[j][0], b[j][1]);
        }
    }

    if (!ATTN) {
#pragma unroll
        for (int i = 0; i < 2; i++) {
            int row = rb * 64 + wm * 32 + i * 16 + grp;
#pragma unroll
            for (int j = 0; j < 4; j++) {
                int col = cb * 128 + wn * 32 + j * 8 + 2 * t4;
                int dir = (col >= 384) ? 1 : 0;
                int g = col - dir * 384;
                float b0v = bias[col], b1v = bias[col + 1];
                if (OH) {
                    uint16_t* o16 = (uint16_t*)outv;
                    *(uint32_t*)&o16[((size_t)dir * nrows + row) * 384 + g] =
                        f2h2(acc[i][j][0] + b0v, acc[i][j][1] + b1v);
                    *(uint32_t*)&o16[((size_t)dir * nrows + row + 8) * 384 + g] =
                        f2h2(acc[i][j][2] + b0v, acc[i][j][3] + b1v);
                } else {
                    float* of = (float*)outv;
                    *(float2*)&of[((size_t)dir * nrows + row) * 384 + g] =
                        make_float2(acc[i][j][0] + b0v, acc[i][j][1] + b1v);
                    *(float2*)&of[((size_t)dir * nrows + row + 8) * 384 + g] =
                        make_float2(acc[i][j][2] + b0v, acc[i][j][3] + b1v);
                }
            }
        }
    } else {
        float* logits = (float*)outv;
        float rsum[2][2];
#pragma unroll
        for (int i = 0; i < 2; i++) { rsum[i][0] = 0.f; rsum[i][1] = 0.f; }
#pragma unroll
        for (int j = 0; j < 4; j++) {
            int col = cb * 128 + wn * 32 + j * 8 + 2 * t4;
            float pv0 = proj[col], pv1 = proj[col + 1];
            float bv0 = bias[col], bv1 = bias[col + 1];
#pragma unroll
            for (int i = 0; i < 2; i++) {
                rsum[i][0] += pv0 * tanhf(acc[i][j][0] + bv0) + pv1 * tanhf(acc[i][j][1] + bv1);
                rsum[i][1] += pv0 * tanhf(acc[i][j][2] + bv0) + pv1 * tanhf(acc[i][j][3] + bv1);
            }
        }
#pragma unroll
        for (int i = 0; i < 2; i++)
#pragma unroll
            for (int sr = 0; sr < 2; sr++) {
                float v = rsum[i][sr];
                v += __shfl_xor_sync(0xffffffffu, v, 1);
                v += __shfl_xor_sync(0xffffffffu, v, 2);
                if (t4 == 0) part_sm[wn][wm * 32 + i * 16 + sr * 8 + grp] = v;
            }
        __syncthreads();
        if (tid < 64)
            logits[(size_t)cb * nrows + rb * 64 + tid] =
                part_sm[0][tid] + part_sm[1][tid] + part_sm[2][tid] + part_sm[3][tid];
    }
}

// ========== K3a: intra biGRU, fp16 tensor recurrence, 64 steps ============
// R12 structure; xg read as fp16, h output written as fp16.
__global__ __launch_bounds__(256) void k_gru_intra_t(const uint16_t* __restrict__ xg,
                                                     const float* __restrict__ Whh,
                                                     const float* __restrict__ bhh,
                                                     uint16_t* __restrict__ out) {
    extern __shared__ uint32_t usm[];
    uint32_t* Ws = usm;                       // 384 x 68 words (half2 [n][kw])
    float* hsm = (float*)(usm + 384 * 68);    // 32 x 132 fp32
    const int bx = blockIdx.x;
    const int dir = bx >> 6, s = (bx >> 1) & 31, bh = bx & 1;
    const int b0 = bh * 32;
    const int tid = threadIdx.x;
    const int lane = tid & 31, w = tid >> 5;
    const int grp = lane >> 2, t4 = lane & 3;

    for (int idx = tid; idx < 384 * 64; idx += 256) {
        int n = idx >> 6, kw = idx & 63;
        const float* p = Whh + dir * 384 * 128 + n * 128 + kw * 2;
        Ws[n * 68 + kw] = f2h2(p[0], p[1]);
    }
    for (int idx = tid; idx < 32 * 132; idx += 256) hsm[idx] = 0.f;
    __syncthreads();

    const int j2 = 16 * w + 2 * t4;
    float br[2][2], bz[2][2], bn[2][2];
#pragma unroll
    for (int jj = 0; jj < 2; jj++)
#pragma unroll
        for (int c = 0; c < 2; c++) {
            int j = j2 + 8 * jj + c;
            br[jj][c] = bhh[dir * 384 + j];
            bz[jj][c] = bhh[dir * 384 + 128 + j];
            bn[jj][c] = bhh[dir * 384 + 256 + j];
        }

    for (int tt = 0; tt < 64; tt++) {
        const int t = dir ? (63 - tt) : tt;
        const uint16_t* xgbase = xg + ((size_t)dir * 131072 + ((s * 64 + t) * 64 + b0)) * 384;

        float2 xr[4][2][3];
#pragma unroll
        for (int ri = 0; ri < 4; ri++) {
            const uint16_t* p = xgbase + (size_t)(grp + 8 * ri) * 384 + j2;
#pragma unroll
            for (int jj = 0; jj < 2; jj++) {
                xr[ri][jj][0] = h2f2(*(const uint32_t*)(p + 8 * jj));
                xr[ri][jj][1] = h2f2(*(const uint32_t*)(p + 128 + 8 * jj));
                xr[ri][jj][2] = h2f2(*(const uint32_t*)(p + 256 + 8 * jj));
            }
        }

        float acc[2][6][4];
#pragma unroll
        for (int i = 0; i < 2; i++)
#pragma unroll
            for (int nt = 0; nt < 6; nt++)
#pragma unroll
                for (int r = 0; r < 4; r++) acc[i][nt][r] = 0.f;

#pragma unroll
        for (int ks = 0; ks < 8; ks++) {          // 8 x k16 over K=128
            uint32_t ah[2][4];
#pragma unroll
            for (int i = 0; i < 2; i++) {
                float2 p0 = *(const float2*)&hsm[(16 * i + grp) * 132 + 16 * ks + 2 * t4];
                float2 p1 = *(const float2*)&hsm[(16 * i + 8 + grp) * 132 + 16 * ks + 2 * t4];
                float2 p2 = *(const float2*)&hsm[(16 * i + grp) * 132 + 16 * ks + 8 + 2 * t4];
                float2 p3 = *(const float2*)&hsm[(16 * i + 8 + grp) * 132 + 16 * ks + 8 + 2 * t4];
                ah[i][0] = f2h2(p0.x, p0.y);
                ah[i][1] = f2h2(p1.x, p1.y);
                ah[i][2] = f2h2(p2.x, p2.y);
                ah[i][3] = f2h2(p3.x, p3.y);
            }
            const int kb = ks * 8;
#pragma unroll
            for (int nt = 0; nt < 6; nt++) {
                int n = 128 * (nt >> 1) + 16 * w + 8 * (nt & 1) + grp;
                uint32_t brg0 = Ws[n * 68 + kb + t4];
                uint32_t brg1 = Ws[n * 68 + kb + 4 + t4];
                mma_f16(acc[0][nt], ah[0][0], ah[0][1], ah[0][2], ah[0][3], brg0, brg1);
                mma_f16(acc[1][nt], ah[1][0], ah[1][1], ah[1][2], ah[1][3], brg0, brg1);
            }
        }

        float hn[2][2][2][2];
#pragma unroll
        for (int i = 0; i < 2; i++)
#pragma unroll
            for (int sr = 0; sr < 2; sr++) {
                int ri = 2 * i + sr;
                int row = 16 * i + 8 * sr + grp;
#pragma unroll
                for (int jj = 0; jj < 2; jj++) {
                    float2 ho = *(const float2*)&hsm[row * 132 + j2 + 8 * jj];
                    float r0 = sigm(xr[ri][jj][0].x + acc[i][jj][2 * sr] + br[jj][0]);
                    float r1 = sigm(xr[ri][jj][0].y + acc[i][jj][2 * sr + 1] + br[jj][1]);
                    float z0 = sigm(xr[ri][jj][1].x + acc[i][2 + jj][2 * sr] + bz[jj][0]);
                    float z1 = sigm(xr[ri][jj][1].y + acc[i][2 + jj][2 * sr + 1] + bz[jj][1]);
                    float n0 = tanhf(xr[ri][jj][2].x + r0 * (acc[i][4 + jj][2 * sr] + bn[jj][0]));
                    float n1 = tanhf(xr[ri][jj][2].y + r1 * (acc[i][4 + jj][2 * sr + 1] + bn[jj][1]));
                    float h0 = (1.f - z0) * n0 + z0 * ho.x;
                    float h1 = (1.f - z1) * n1 + z1 * ho.y;
                    hn[i][sr][jj][0] = h0;
                    hn[i][sr][jj][1] = h1;
                    *(uint32_t*)&out[(((size_t)(s * 64 + t)) * 64 + b0 + row) * 256 +
                                     dir * 128 + j2 + 8 * jj] = f2h2(h0, h1);
                }
            }
        __syncthreads();
#pragma unroll
        for (int i = 0; i < 2; i++)
#pragma unroll
            for (int sr = 0; sr < 2; sr++) {
                int row = 16 * i + 8 * sr + grp;
#pragma unroll
                for (int jj = 0; jj < 2; jj++)
                    *(float2*)&hsm[row * 132 + j2 + 8 * jj] =
                        make_float2(hn[i][sr][jj][0], hn[i][sr][jj][1]);
            }
        __syncthreads();
    }
}

// ---------------- K3b: inter biGRU (small, SIMT) --------------------------
__global__ void k_gru_inter(const float* __restrict__ xg,
                            const float* __restrict__ Whh,
                            const float* __restrict__ bhh,
                            float* __restrict__ out) {
    extern __shared__ float sm[];
    float* Ws = sm;              // 384*133
    float* hs = sm + 384 * 133;  // 2*132
    const int bx = blockIdx.x;
    const int dir = bx >> 5;
    const int b0 = (bx & 31) * 2;
    const int tid = threadIdx.x;
    const int bl = tid >> 7;
    const int j = tid & 127;

    for (int idx = tid; idx < 384 * 128; idx += 256) {
        int row = idx >> 7, k = idx & 127;
        Ws[row * 133 + k] = Whh[dir * 384 * 128 + idx];
    }
    for (int idx = tid; idx < 2 * 132; idx += 256) hs[idx] = 0.f;
    __syncthreads();

    const float br = bhh[dir * 384 + j];
    const float bz = bhh[dir * 384 + 128 + j];
    const float bn = bhh[dir * 384 + 256 + j];

    for (int tt = 0; tt < 32; tt++) {
        const int sstep = dir ? (31 - tt) : tt;
        float ar = 0.f, az = 0.f, an = 0.f;
#pragma unroll 4
        for (int k = 0; k < 128; k++) {
            float hv = hs[bl * 132 + k];
            int ro = j * 133 + k;
            ar = fmaf(hv, Ws[ro], ar);
            az = fmaf(hv, Ws[ro + 128 * 133], az);
            an = fmaf(hv, Ws[ro + 256 * 133], an);
        }
        const int b = b0 + bl;
        const float* xr = xg + (((size_t)dir * 32 + sstep) * 64 + b) * 384;
        float r = sigm(xr[j] + ar + br);
        float z = sigm(xr[128 + j] + az + bz);
        float n = tanhf(xr[256 + j] + r * (an + bn));
        float ho = hs[bl * 132 + j];
        float hv2 = (1.f - z) * n + z * ho;
        out[((size_t)sstep * 64 + b) * 256 + dir * 128 + j] = hv2;
        __syncthreads();
        hs[bl * 132 + j] = hv2;
        __syncthreads();
    }
}

// ------- softmax over t (sums 2 partial planes, writes plane 0) -----------
__global__ void k_softmax_t(float* __restrict__ a) {
    const int NP = S_ * T_ * B_;
    int gid = blockIdx.x * blockDim.x + threadIdx.x;
    if (gid >= S_ * B_) return;
    int s = gid >> 6, b = gid & 63;
    size_t base = (size_t)s * 4096 + b;
    float mx = -1e30f;
    for (int t = 0; t < 64; t++) {
        float v = a[base + t * 64] + a[NP + base + t * 64];
        mx = fmaxf(mx, v);
    }
    float sum = 0.f;
    for (int t = 0; t < 64; t++) {
        float v = a[base + t * 64] + a[NP + base + t * 64];
        sum += expf(v - mx);
    }
    float inv = 1.f / sum;
    for (int t = 0; t < 64; t++) {
        float v = a[base + t * 64] + a[NP + base + t * 64];
        a[base + t * 64] = expf(v - mx) * inv;
    }
}

// ---------------- sentence vectors: sum_t a1 * X (X fp16) ------------------
__global__ void k_sent(const float* __restrict__ a1,
                       const uint16_t* __restrict__ X,
                       float* __restrict__ sent) {
    const int s = blockIdx.x, bg = blockIdx.y;
    const int h = threadIdx.x;
    float acc[8];
#pragma unroll
    for (int ib = 0; ib < 8; ib++) acc[ib] = 0.f;
    for (int t = 0; t < 64; t++) {
#pragma unroll
        for (int ib = 0; ib < 8; ib++) {
            int b = bg * 8 + ib;
            size_t row = (size_t)s * 4096 + (size_t)t * 64 + b;
            __half hv = *(const __half*)&X[row * 256 + h];
            acc[ib] = fmaf(a1[row], __half2float(hv), acc[ib]);
        }
    }
#pragma unroll
    for (int ib = 0; ib < 8; ib++)
        sent[((size_t)s * 64 + bg * 8 + ib) * 256 + h] = acc[ib];
}

// --------- doc vector + final linear (sums 2 partial a2 planes) -----------
__global__ void k_doc_final(const float* __restrict__ a2,
                            const float* __restrict__ Xo,
                            const float* __restrict__ Wf,
                            const float* __restrict__ bf,
                            float* __restrict__ outp) {
    __shared__ float red[256];
    const int b = blockIdx.x, h = threadIdx.x;
    float dh = 0.f;
    for (int s2 = 0; s2 < 32; s2++) {
        size_t row = (size_t)s2 * 64 + b;
        float av = a2[row] + a2[S_ * B_ + row];
        dh = fmaf(av, Xo[row * 256 + h], dh);
    }
    for (int c = 0; c < C_; c++) {
        red[h] = dh * Wf[c * 256 + h];
        __syncthreads();
        for (int off = 128; off > 0; off >>= 1) {
            if (h < off) red[h] += red[h + off];
            __syncthreads();
        }
        if (h == 0) outp[b * C_ + c] = red[0] + bf[c];
        __syncthreads();
    }
}

// ---------------- launch ---------------------------------------------------
extern "C" void kernel_launch(void* const* d_in, const int* in_sizes, int n_in,
                              void* d_out, int out_size) {
    const int*   tokens = (const int*)d_in[0];
    const float* embed  = (const float*)d_in[1];
    const float* Wih_a  = (const float*)d_in[2];
    const float* Whh_a  = (const float*)d_in[3];
    const float* bih_a  = (const float*)d_in[4];
    const float* bhh_a  = (const float*)d_in[5];
    const float* WW_a   = (const float*)d_in[6];
    const float* b_a    = (const float*)d_in[7];
    const float* proj_a = (const float*)d_in[8];
    const float* Wih_e  = (const float*)d_in[9];
    const float* Whh_e  = (const float*)d_in[10];
    const float* bih_e  = (const float*)d_in[11];
    const float* bhh_e  = (const float*)d_in[12];
    const float* WW_e   = (const float*)d_in[13];
    const float* b_e    = (const float*)d_in[14];
    const float* proj_e = (const float*)d_in[15];
    const float* Wf     = (const float*)d_in[16];
    const float* bf     = (const float*)d_in[17];
    float* outp = (float*)d_out;

    void *xgh_p, *ioh_p, *a1_p, *sent_p, *xge_p, *ioe_p, *a2_p;
    void *embh_p, *wihA_p, *wihE_p, *ww_p;
    cudaGetSymbolAddress(&xgh_p, g_xg_h);
    cudaGetSymbolAddress(&ioh_p, g_io_h);
    cudaGetSymbolAddress(&a1_p, g_a1p);
    cudaGetSymbolAddress(&sent_p, g_sent);
    cudaGetSymbolAddress(&xge_p, g_xg_inter);
    cudaGetSymbolAddress(&ioe_p, g_inter_out);
    cudaGetSymbolAddress(&a2_p, g_a2p);
    cudaGetSymbolAddress(&embh_p, g_emb_h);
    cudaGetSymbolAddress(&wihA_p, g_wihA_h);
    cudaGetSymbolAddress(&wihE_p, g_wihE_h);
    cudaGetSymbolAddress(&ww_p, g_ww_h);

    const int sm_gemm  = (64 * 36 + 128 * 36) * 4;    // 27648
    const int sm_intra = (384 * 68 + 32 * 132) * 4;   // 121344
    const int sm_inter = (384 * 133 + 2 * 132) * 4;
    cudaFuncSetAttribute((const void*)k_gemm4<128, false, true, true>,
                         cudaFuncAttributeMaxDynamicSharedMemorySize, sm_gemm);
    cudaFuncSetAttribute((const void*)k_gemm4<256, true, true, false>,
                         cudaFuncAttributeMaxDynamicSharedMemorySize, sm_gemm);
    cudaFuncSetAttribute((const void*)k_gemm4<256, false, false, false>,
                         cudaFuncAttributeMaxDynamicSharedMemorySize, sm_gemm);
    cudaFuncSetAttribute((const void*)k_gemm4<256, true, false, false>,
                         cudaFuncAttributeMaxDynamicSharedMemorySize, sm_gemm);
    cudaFuncSetAttribute(k_gru_intra_t, cudaFuncAttributeMaxDynamicSharedMemorySize, sm_intra);
    cudaFuncSetAttribute(k_gru_inter, cudaFuncAttributeMaxDynamicSharedMemorySize, sm_inter);

    // 0) one-time fp16 conversions
    k_prep_h<<<2000, 256>>>(embed, (uint16_t*)embh_p);
    k_prep_h<<<48, 256>>>(Wih_a, (uint16_t*)wihA_p);
    k_prep_h<<<96, 256>>>(Wih_e, (uint16_t*)wihE_p);
    k_prep_ww_h<<<dim3(256, 2), 256>>>(WW_a, WW_e, (uint16_t*)ww_p);
    // 1) intra input gates: gathered fp16 GEMM -> fp16 xg, rows = 131072
    k_gemm4<128, false, true, true><<<dim3(2048, 6), 256, sm_gemm>>>(
        tokens, (uint16_t*)embh_p, (uint16_t*)wihA_p, bih_a, nullptr,
        xgh_p, 131072);
    // 2) intra biGRU (fp16 tensor recurrence; fp16 xg in, fp16 h out)
    k_gru_intra_t<<<128, 256, sm_intra>>>((uint16_t*)xgh_p, Whh_a, bhh_a,
                                          (uint16_t*)ioh_p);
    // 3) word attention partial logits (fp16 A copy; 2 col-halves -> 2 planes)
    k_gemm4<256, true, true, false><<<dim3(2048, 2), 256, sm_gemm>>>(
        nullptr, (uint16_t*)ioh_p, (uint16_t*)ww_p, b_a, proj_a, a1_p, 131072);
    // 4) softmax over tokens (sums planes)
    k_softmax_t<<<8, 256>>>((float*)a1_p);
    // 5) sentence vectors (fp16 X)
    k_sent<<<dim3(32, 8), 256>>>((float*)a1_p, (uint16_t*)ioh_p, (float*)sent_p);
    // 6) inter input gates: rows = 2048 (fp32 in/out)
    k_gemm4<256, false, false, false><<<dim3(32, 6), 256, sm_gemm>>>(
        nullptr, (float*)sent_p, (uint16_t*)wihE_p, bih_e, nullptr,
        xge_p, 2048);
    // 7) inter biGRU
    k_gru_inter<<<64, 256, sm_inter>>>((float*)xge_p, Whh_e, bhh_e, (float*)ioe_p);
    // 8) sentence attention partial logits (NO softmax)
    k_gemm4<256, true, false, false><<<dim3(32, 2), 256, sm_gemm>>>(
        nullptr, (float*)ioe_p, (uint16_t*)ww_p + 65536, b_e, proj_e, a2_p, 2048);
    // 9) doc vector + final linear
    k_doc_final<<<64, 256>>>((float*)a2_p, (float*)ioe_p, Wf, bf, outp);
}

// round 15
// speedup vs baseline: 1.7075x; 1.1085x over previous
#include <cuda_runtime.h>
#include <cuda_fp16.h>
#include <math.h>
#include <stdint.h>

#define S_  32
#define T_  64
#define B_  64
#define C_  5
#define VOCAB_ 32000

// ---------------- scratch (device globals; no allocation) ----------------
__device__ uint16_t g_xg_h[(size_t)2*S_*T_*B_*384]; // fp16 [dir][row(s,t,b)][384]
__device__ uint16_t g_io_h[(size_t)S_*T_*B_*256];   // fp16 [s][t][b][256] fwd|bwd
__device__ float g_a1p[2*S_*T_*B_];                 // 2 partial planes
__device__ float g_sent[S_*B_*256];
__device__ float g_xg_inter[2*S_*B_*384];
__device__ float g_inter_out[S_*B_*256];
__device__ float g_a2p[2*S_*B_];
// fp16 preconversions
__device__ uint16_t g_emb_h[(size_t)VOCAB_*128];    // embed table half
__device__ uint16_t g_wihA_h[768*128];              // Wih_a half [col][k]
__device__ uint16_t g_wihE_h[768*256];              // Wih_e half [col][k]
__device__ uint16_t g_ww_h[2*256*256];              // WW_a/WW_e transposed half [n][k]

__device__ __forceinline__ float sigm(float x) { return 1.f / (1.f + expf(-x)); }

__device__ __forceinline__ uint32_t f2h2(float x, float y) {
    __half2 h = __floats2half2_rn(x, y);
    return *(uint32_t*)&h;
}
__device__ __forceinline__ float2 h2f2(uint32_t u) {
    return __half22float2(*(__half2*)&u);
}

__device__ __forceinline__ void mma_f16(float c[4],
                                        uint32_t a0, uint32_t a1, uint32_t a2, uint32_t a3,
                                        uint32_t b0, uint32_t b1) {
    asm volatile(
        "mma.sync.aligned.m16n8k16.row.col.f32.f16.f16.f32 "
        "{%0,%1,%2,%3}, {%4,%5,%6,%7}, {%8,%9}, {%0,%1,%2,%3};"
        : "+f"(c[0]), "+f"(c[1]), "+f"(c[2]), "+f"(c[3])
        : "r"(a0), "r"(a1), "r"(a2), "r"(a3), "r"(b0), "r"(b1));
}

// ---- prep kernels: one-time fp16 conversions ------------------------------
__global__ void k_prep_h(const float* __restrict__ in, uint16_t* __restrict__ out) {
    size_t q = ((size_t)blockIdx.x * 256 + threadIdx.x) * 8;
    float4 v0 = *(const float4*)(in + q);
    float4 v1 = *(const float4*)(in + q + 4);
    uint4 u = make_uint4(f2h2(v0.x, v0.y), f2h2(v0.z, v0.w),
                         f2h2(v1.x, v1.y), f2h2(v1.z, v1.w));
    *(uint4*)(out + q) = u;
}
__global__ void k_prep_ww_h(const float* __restrict__ Wa, const float* __restrict__ We,
                            uint16_t* __restrict__ out) {
    int idx = blockIdx.x * 256 + threadIdx.x;       // 0..65535
    const float* W = blockIdx.y ? We : Wa;
    int n = idx >> 8, h = idx & 255;
    __half v = __float2half_rn(W[h * 256 + n]);
    out[blockIdx.y * 65536 + n * 256 + h] = *(uint16_t*)&v;
}

// ============ unified fp16 tensor GEMM: 64x128 tiles, 3 blocks/SM =========
template<int KDIM, bool ATTN, bool AHALF, bool OH>
__global__ __launch_bounds__(256, 3) void k_gemm4(const int* __restrict__ tokens,
                                                  const void* __restrict__ Av,
                                                  const uint16_t* __restrict__ Wt,
                                                  const float* __restrict__ bias,
                                                  const float* __restrict__ proj,
                                                  void* __restrict__ outv,
                                                  int nrows) {
    extern __shared__ uint32_t usm[];
    uint32_t* As = usm;              // 64 rows x 36 words (64-k chunk as half2)
    uint32_t* Bs = usm + 64 * 36;    // 128 cols x 36 words
    __shared__ int toks[64];
    __shared__ float part_sm[4][65];
    const int rb = blockIdx.x, cb = blockIdx.y;
    const int tid = threadIdx.x;
    const int lane = tid & 31, wid = tid >> 5;
    const int wm = wid >> 2, wn = wid & 3;   // 2 (M) x 4 (N)
    const int grp = lane >> 2, t4 = lane & 3;

    if (tokens) {
        if (tid < 64) toks[tid] = tokens[rb * 64 + tid];
        __syncthreads();
    }

    float acc[2][4][4];
#pragma unroll
    for (int i = 0; i < 2; i++)
#pragma unroll
        for (int j = 0; j < 4; j++)
#pragma unroll
            for (int r = 0; r < 4; r++) acc[i][j][r] = 0.f;

#pragma unroll
    for (int kc = 0; kc < KDIM / 64; kc++) {
        if (kc) __syncthreads();
        for (int q = tid; q < 64 * 8; q += 256) {
            int r = q >> 3, u = q & 7;
            size_t rowbase = tokens ? (size_t)toks[r] * KDIM
                                    : (size_t)(rb * 64 + r) * KDIM;
            if (AHALF) {
                uint4 v = *(const uint4*)((const uint16_t*)Av + rowbase + kc * 64 + u * 8);
                *(uint4*)(As + r * 36 + u * 4) = v;
            } else {
                const float* src = (const float*)Av + rowbase + kc * 64 + u * 8;
                float4 v0 = *(const float4*)src;
                float4 v1 = *(const float4*)(src + 4);
                *(uint4*)(As + r * 36 + u * 4) =
                    make_uint4(f2h2(v0.x, v0.y), f2h2(v0.z, v0.w),
                               f2h2(v1.x, v1.y), f2h2(v1.z, v1.w));
            }
        }
        for (int q = tid; q < 128 * 8; q += 256) {
            int n = q >> 3, u = q & 7;
            uint4 v = *(const uint4*)(Wt + (size_t)(cb * 128 + n) * KDIM + kc * 64 + u * 8);
            *(uint4*)(Bs + n * 36 + u * 4) = v;
        }
        __syncthreads();
#pragma unroll
        for (int ks = 0; ks < 4; ks++) {
            const int kb = ks * 8;
            uint32_t a[2][4], b[4][2];
#pragma unroll
            for (int i = 0; i < 2; i++) {
                int row = wm * 32 + i * 16 + grp;
                a[i][0] = As[row * 36 + kb + t4];
                a[i][1] = As[(row + 8) * 36 + kb + t4];
                a[i][2] = As[row * 36 + kb + 4 + t4];
                a[i][3] = As[(row + 8) * 36 + kb + 4 + t4];
            }
#pragma unroll
            for (int j = 0; j < 4; j++) {
                int n = wn * 32 + j * 8 + grp;
                b[j][0] = Bs[n * 36 + kb + t4];
                b[j][1] = Bs[n * 36 + kb + 4 + t4];
            }
#pragma unroll
            for (int i = 0; i < 2; i++)
#pragma unroll
                for (int j = 0; j < 4; j++)
                    mma_f16(acc[i][j], a[i][0], a[i][1], a[i][2], a[i][3], b[j][0], b[j][1]);
        }
    }

    if (!ATTN) {
#pragma unroll
        for (int i = 0; i < 2; i++) {
            int row = rb * 64 + wm * 32 + i * 16 + grp;
#pragma unroll
            for (int j = 0; j < 4; j++) {
                int col = cb * 128 + wn * 32 + j * 8 + 2 * t4;
                int dir = (col >= 384) ? 1 : 0;
                int g = col - dir * 384;
                float b0v = bias[col], b1v = bias[col + 1];
                if (OH) {
                    uint16_t* o16 = (uint16_t*)outv;
                    *(uint32_t*)&o16[((size_t)dir * nrows + row) * 384 + g] =
                        f2h2(acc[i][j][0] + b0v, acc[i][j][1] + b1v);
                    *(uint32_t*)&o16[((size_t)dir * nrows + row + 8) * 384 + g] =
                        f2h2(acc[i][j][2] + b0v, acc[i][j][3] + b1v);
                } else {
                    float* of = (float*)outv;
                    *(float2*)&of[((size_t)dir * nrows + row) * 384 + g] =
                        make_float2(acc[i][j][0] + b0v, acc[i][j][1] + b1v);
                    *(float2*)&of[((size_t)dir * nrows + row + 8) * 384 + g] =
                        make_float2(acc[i][j][2] + b0v, acc[i][j][3] + b1v);
                }
            }
        }
    } else {
        float* logits = (float*)outv;
        float rsum[2][2];
#pragma unroll
        for (int i = 0; i < 2; i++) { rsum[i][0] = 0.f; rsum[i][1] = 0.f; }
#pragma unroll
        for (int j = 0; j < 4; j++) {
            int col = cb * 128 + wn * 32 + j * 8 + 2 * t4;
            float pv0 = proj[col], pv1 = proj[col + 1];
            float bv0 = bias[col], bv1 = bias[col + 1];
#pragma unroll
            for (int i = 0; i < 2; i++) {
                rsum[i][0] += pv0 * tanhf(acc[i][j][0] + bv0) + pv1 * tanhf(acc[i][j][1] + bv1);
                rsum[i][1] += pv0 * tanhf(acc[i][j][2] + bv0) + pv1 * tanhf(acc[i][j][3] + bv1);
            }
        }
#pragma unroll
        for (int i = 0; i < 2; i++)
#pragma unroll
            for (int sr = 0; sr < 2; sr++) {
                float v = rsum[i][sr];
                v += __shfl_xor_sync(0xffffffffu, v, 1);
                v += __shfl_xor_sync(0xffffffffu, v, 2);
                if (t4 == 0) part_sm[wn][wm * 32 + i * 16 + sr * 8 + grp] = v;
            }
        __syncthreads();
        if (tid < 64)
            logits[(size_t)cb * nrows + rb * 64 + tid] =
                part_sm[0][tid] + part_sm[1][tid] + part_sm[2][tid] + part_sm[3][tid];
    }
}

// ========== K3a: intra biGRU, fp16 tensor recurrence, 64 steps ============
// 16 batch rows / block -> grid 256, 2 blocks/SM (epilogue overlaps mma).
__global__ __launch_bounds__(256, 2) void k_gru_intra_t(const uint16_t* __restrict__ xg,
                                                        const float* __restrict__ Whh,
                                                        const float* __restrict__ bhh,
                                                        uint16_t* __restrict__ out) {
    extern __shared__ uint32_t usm[];
    uint32_t* Ws = usm;                       // 384 x 68 words (half2 [n][kw])
    float* hsm = (float*)(usm + 384 * 68);    // 16 x 132 fp32
    const int bx = blockIdx.x;
    const int dir = bx >> 7, s = (bx >> 2) & 31, qt = bx & 3;
    const int b0 = qt * 16;
    const int tid = threadIdx.x;
    const int lane = tid & 31, w = tid >> 5;
    const int grp = lane >> 2, t4 = lane & 3;

    for (int idx = tid; idx < 384 * 64; idx += 256) {
        int n = idx >> 6, kw = idx & 63;
        const float* p = Whh + dir * 384 * 128 + n * 128 + kw * 2;
        Ws[n * 68 + kw] = f2h2(p[0], p[1]);
    }
    for (int idx = tid; idx < 16 * 132; idx += 256) hsm[idx] = 0.f;
    __syncthreads();

    const int j2 = 16 * w + 2 * t4;
    float br[2][2], bz[2][2], bn[2][2];
#pragma unroll
    for (int jj = 0; jj < 2; jj++)
#pragma unroll
        for (int c = 0; c < 2; c++) {
            int j = j2 + 8 * jj + c;
            br[jj][c] = bhh[dir * 384 + j];
            bz[jj][c] = bhh[dir * 384 + 128 + j];
            bn[jj][c] = bhh[dir * 384 + 256 + j];
        }

    for (int tt = 0; tt < 64; tt++) {
        const int t = dir ? (63 - tt) : tt;
        const uint16_t* xgbase = xg + ((size_t)dir * 131072 + ((s * 64 + t) * 64 + b0)) * 384;

        float2 xr[2][2][3];   // [sr][jj][gate]
#pragma unroll
        for (int sr = 0; sr < 2; sr++) {
            const uint16_t* p = xgbase + (size_t)(grp + 8 * sr) * 384 + j2;
#pragma unroll
            for (int jj = 0; jj < 2; jj++) {
                xr[sr][jj][0] = h2f2(*(const uint32_t*)(p + 8 * jj));
                xr[sr][jj][1] = h2f2(*(const uint32_t*)(p + 128 + 8 * jj));
                xr[sr][jj][2] = h2f2(*(const uint32_t*)(p + 256 + 8 * jj));
            }
        }

        float acc[6][4];
#pragma unroll
        for (int nt = 0; nt < 6; nt++)
#pragma unroll
            for (int r = 0; r < 4; r++) acc[nt][r] = 0.f;

#pragma unroll
        for (int ks = 0; ks < 8; ks++) {          // 8 x k16 over K=128
            uint32_t ah[4];
            {
                float2 p0 = *(const float2*)&hsm[grp * 132 + 16 * ks + 2 * t4];
                float2 p1 = *(const float2*)&hsm[(8 + grp) * 132 + 16 * ks + 2 * t4];
                float2 p2 = *(const float2*)&hsm[grp * 132 + 16 * ks + 8 + 2 * t4];
                float2 p3 = *(const float2*)&hsm[(8 + grp) * 132 + 16 * ks + 8 + 2 * t4];
                ah[0] = f2h2(p0.x, p0.y);
                ah[1] = f2h2(p1.x, p1.y);
                ah[2] = f2h2(p2.x, p2.y);
                ah[3] = f2h2(p3.x, p3.y);
            }
            const int kb = ks * 8;
#pragma unroll
            for (int nt = 0; nt < 6; nt++) {
                int n = 128 * (nt >> 1) + 16 * w + 8 * (nt & 1) + grp;
                uint32_t brg0 = Ws[n * 68 + kb + t4];
                uint32_t brg1 = Ws[n * 68 + kb + 4 + t4];
                mma_f16(acc[nt], ah[0], ah[1], ah[2], ah[3], brg0, brg1);
            }
        }

        float hn[2][2][2];   // [sr][jj][c]
#pragma unroll
        for (int sr = 0; sr < 2; sr++) {
            int row = 8 * sr + grp;
#pragma unroll
            for (int jj = 0; jj < 2; jj++) {
                float2 ho = *(const float2*)&hsm[row * 132 + j2 + 8 * jj];
                float r0 = sigm(xr[sr][jj][0].x + acc[jj][2 * sr] + br[jj][0]);
                float r1 = sigm(xr[sr][jj][0].y + acc[jj][2 * sr + 1] + br[jj][1]);
                float z0 = sigm(xr[sr][jj][1].x + acc[2 + jj][2 * sr] + bz[jj][0]);
                float z1 = sigm(xr[sr][jj][1].y + acc[2 + jj][2 * sr + 1] + bz[jj][1]);
                float n0 = tanhf(xr[sr][jj][2].x + r0 * (acc[4 + jj][2 * sr] + bn[jj][0]));
                float n1 = tanhf(xr[sr][jj][2].y + r1 * (acc[4 + jj][2 * sr + 1] + bn[jj][1]));
                float h0 = (1.f - z0) * n0 + z0 * ho.x;
                float h1 = (1.f - z1) * n1 + z1 * ho.y;
                hn[sr][jj][0] = h0;
                hn[sr][jj][1] = h1;
                *(uint32_t*)&out[(((size_t)(s * 64 + t)) * 64 + b0 + row) * 256 +
                                 dir * 128 + j2 + 8 * jj] = f2h2(h0, h1);
            }
        }
        __syncthreads();
#pragma unroll
        for (int sr = 0; sr < 2; sr++) {
            int row = 8 * sr + grp;
#pragma unroll
            for (int jj = 0; jj < 2; jj++)
                *(float2*)&hsm[row * 132 + j2 + 8 * jj] =
                    make_float2(hn[sr][jj][0], hn[sr][jj][1]);
        }
        __syncthreads();
    }
}

// ---------------- K3b: inter biGRU (small, SIMT) --------------------------
__global__ void k_gru_inter(const float* __restrict__ xg,
                            const float* __restrict__ Whh,
                            const float* __restrict__ bhh,
                            float* __restrict__ out) {
    extern __shared__ float sm[];
    float* Ws = sm;              // 384*133
    float* hs = sm + 384 * 133;  // 2*132
    const int bx = blockIdx.x;
    const int dir = bx >> 5;
    const int b0 = (bx & 31) * 2;
    const int tid = threadIdx.x;
    const int bl = tid >> 7;
    const int j = tid & 127;

    for (int idx = tid; idx < 384 * 128; idx += 256) {
        int row = idx >> 7, k = idx & 127;
        Ws[row * 133 + k] = Whh[dir * 384 * 128 + idx];
    }
    for (int idx = tid; idx < 2 * 132; idx += 256) hs[idx] = 0.f;
    __syncthreads();

    const float br = bhh[dir * 384 + j];
    const float bz = bhh[dir * 384 + 128 + j];
    const float bn = bhh[dir * 384 + 256 + j];

    for (int tt = 0; tt < 32; tt++) {
        const int sstep = dir ? (31 - tt) : tt;
        float ar = 0.f, az = 0.f, an = 0.f;
#pragma unroll 4
        for (int k = 0; k < 128; k++) {
            float hv = hs[bl * 132 + k];
            int ro = j * 133 + k;
            ar = fmaf(hv, Ws[ro], ar);
            az = fmaf(hv, Ws[ro + 128 * 133], az);
            an = fmaf(hv, Ws[ro + 256 * 133], an);
        }
        const int b = b0 + bl;
        const float* xr = xg + (((size_t)dir * 32 + sstep) * 64 + b) * 384;
        float r = sigm(xr[j] + ar + br);
        float z = sigm(xr[128 + j] + az + bz);
        float n = tanhf(xr[256 + j] + r * (an + bn));
        float ho = hs[bl * 132 + j];
        float hv2 = (1.f - z) * n + z * ho;
        out[((size_t)sstep * 64 + b) * 256 + dir * 128 + j] = hv2;
        __syncthreads();
        hs[bl * 132 + j] = hv2;
        __syncthreads();
    }
}

// ------- softmax over t (sums 2 partial planes, writes plane 0) -----------
__global__ void k_softmax_t(float* __restrict__ a) {
    const int NP = S_ * T_ * B_;
    int gid = blockIdx.x * blockDim.x + threadIdx.x;
    if (gid >= S_ * B_) return;
    int s = gid >> 6, b = gid & 63;
    size_t base = (size_t)s * 4096 + b;
    float mx = -1e30f;
    for (int t = 0; t < 64; t++) {
        float v = a[base + t * 64] + a[NP + base + t * 64];
        mx = fmaxf(mx, v);
    }
    float sum = 0.f;
    for (int t = 0; t < 64; t++) {
        float v = a[base + t * 64] + a[NP + base + t * 64];
        sum += expf(v - mx);
    }
    float inv = 1.f / sum;
    for (int t = 0; t < 64; t++) {
        float v = a[base + t * 64] + a[NP + base + t * 64];
        a[base + t * 64] = expf(v - mx) * inv;
    }
}

// ---------------- sentence vectors: sum_t a1 * X (X fp16) ------------------
__global__ void k_sent(const float* __restrict__ a1,
                       const uint16_t* __restrict__ X,
                       float* __restrict__ sent) {
    const int s = blockIdx.x, bg = blockIdx.y;
    const int h = threadIdx.x;
    float acc[8];
#pragma unroll
    for (int ib = 0; ib < 8; ib++) acc[ib] = 0.f;
    for (int t = 0; t < 64; t++) {
#pragma unroll
        for (int ib = 0; ib < 8; ib++) {
            int b = bg * 8 + ib;
            size_t row = (size_t)s * 4096 + (size_t)t * 64 + b;
            __half hv = *(const __half*)&X[row * 256 + h];
            acc[ib] = fmaf(a1[row], __half2float(hv), acc[ib]);
        }
    }
#pragma unroll
    for (int ib = 0; ib < 8; ib++)
        sent[((size_t)s * 64 + bg * 8 + ib) * 256 + h] = acc[ib];
}

// --------- doc vector + final linear (sums 2 partial a2 planes) -----------
__global__ void k_doc_final(const float* __restrict__ a2,
                            const float* __restrict__ Xo,
                            const float* __restrict__ Wf,
                            const float* __restrict__ bf,
                            float* __restrict__ outp) {
    __shared__ float red[256];
    const int b = blockIdx.x, h = threadIdx.x;
    float dh = 0.f;
    for (int s2 = 0; s2 < 32; s2++) {
        size_t row = (size_t)s2 * 64 + b;
        float av = a2[row] + a2[S_ * B_ + row];
        dh = fmaf(av, Xo[row * 256 + h], dh);
    }
    for (int c = 0; c < C_; c++) {
        red[h] = dh * Wf[c * 256 + h];
        __syncthreads();
        for (int off = 128; off > 0; off >>= 1) {
            if (h < off) red[h] += red[h + off];
            __syncthreads();
        }
        if (h == 0) outp[b * C_ + c] = red[0] + bf[c];
        __syncthreads();
    }
}

// ---------------- launch ---------------------------------------------------
extern "C" void kernel_launch(void* const* d_in, const int* in_sizes, int n_in,
                              void* d_out, int out_size) {
    const int*   tokens = (const int*)d_in[0];
    const float* embed  = (const float*)d_in[1];
    const float* Wih_a  = (const float*)d_in[2];
    const float* Whh_a  = (const float*)d_in[3];
    const float* bih_a  = (const float*)d_in[4];
    const float* bhh_a  = (const float*)d_in[5];
    const float* WW_a   = (const float*)d_in[6];
    const float* b_a    = (const float*)d_in[7];
    const float* proj_a = (const float*)d_in[8];
    const float* Wih_e  = (const float*)d_in[9];
    const float* Whh_e  = (const float*)d_in[10];
    const float* bih_e  = (const float*)d_in[11];
    const float* bhh_e  = (const float*)d_in[12];
    const float* WW_e   = (const float*)d_in[13];
    const float* b_e    = (const float*)d_in[14];
    const float* proj_e = (const float*)d_in[15];
    const float* Wf     = (const float*)d_in[16];
    const float* bf     = (const float*)d_in[17];
    float* outp = (float*)d_out;

    void *xgh_p, *ioh_p, *a1_p, *sent_p, *xge_p, *ioe_p, *a2_p;
    void *embh_p, *wihA_p, *wihE_p, *ww_p;
    cudaGetSymbolAddress(&xgh_p, g_xg_h);
    cudaGetSymbolAddress(&ioh_p, g_io_h);
    cudaGetSymbolAddress(&a1_p, g_a1p);
    cudaGetSymbolAddress(&sent_p, g_sent);
    cudaGetSymbolAddress(&xge_p, g_xg_inter);
    cudaGetSymbolAddress(&ioe_p, g_inter_out);
    cudaGetSymbolAddress(&a2_p, g_a2p);
    cudaGetSymbolAddress(&embh_p, g_emb_h);
    cudaGetSymbolAddress(&wihA_p, g_wihA_h);
    cudaGetSymbolAddress(&wihE_p, g_wihE_h);
    cudaGetSymbolAddress(&ww_p, g_ww_h);

    const int sm_gemm  = (64 * 36 + 128 * 36) * 4;    // 27648
    const int sm_intra = (384 * 68 + 16 * 132) * 4;   // 112896
    const int sm_inter = (384 * 133 + 2 * 132) * 4;
    cudaFuncSetAttribute((const void*)k_gemm4<128, false, true, true>,
                         cudaFuncAttributeMaxDynamicSharedMemorySize, sm_gemm);
    cudaFuncSetAttribute((const void*)k_gemm4<256, true, true, false>,
                         cudaFuncAttributeMaxDynamicSharedMemorySize, sm_gemm);
    cudaFuncSetAttribute((const void*)k_gemm4<256, false, false, false>,
                         cudaFuncAttributeMaxDynamicSharedMemorySize, sm_gemm);
    cudaFuncSetAttribute((const void*)k_gemm4<256, true, false, false>,
                         cudaFuncAttributeMaxDynamicSharedMemorySize, sm_gemm);
    cudaFuncSetAttribute(k_gru_intra_t, cudaFuncAttributeMaxDynamicSharedMemorySize, sm_intra);
    cudaFuncSetAttribute(k_gru_inter, cudaFuncAttributeMaxDynamicSharedMemorySize, sm_inter);

    // 0) one-time fp16 conversions
    k_prep_h<<<2000, 256>>>(embed, (uint16_t*)embh_p);
    k_prep_h<<<48, 256>>>(Wih_a, (uint16_t*)wihA_p);
    k_prep_h<<<96, 256>>>(Wih_e, (uint16_t*)wihE_p);
    k_prep_ww_h<<<dim3(256, 2), 256>>>(WW_a, WW_e, (uint16_t*)ww_p);
    // 1) intra input gates: gathered fp16 GEMM -> fp16 xg, rows = 131072
    k_gemm4<128, false, true, true><<<dim3(2048, 6), 256, sm_gemm>>>(
        tokens, (uint16_t*)embh_p, (uint16_t*)wihA_p, bih_a, nullptr,
        xgh_p, 131072);
    // 2) intra biGRU (fp16 tensor recurrence; 16 rows/block, 2 blocks/SM)
    k_gru_intra_t<<<256, 256, sm_intra>>>((uint16_t*)xgh_p, Whh_a, bhh_a,
                                          (uint16_t*)ioh_p);
    // 3) word attention partial logits (fp16 A copy; 2 col-halves -> 2 planes)
    k_gemm4<256, true, true, false><<<dim3(2048, 2), 256, sm_gemm>>>(
        nullptr, (uint16_t*)ioh_p, (uint16_t*)ww_p, b_a, proj_a, a1_p, 131072);
    // 4) softmax over tokens (sums planes)
    k_softmax_t<<<8, 256>>>((float*)a1_p);
    // 5) sentence vectors (fp16 X)
    k_sent<<<dim3(32, 8), 256>>>((float*)a1_p, (uint16_t*)ioh_p, (float*)sent_p);
    // 6) inter input gates: rows = 2048 (fp32 in/out)
    k_gemm4<256, false, false, false><<<dim3(32, 6), 256, sm_gemm>>>(
        nullptr, (float*)sent_p, (uint16_t*)wihE_p, bih_e, nullptr,
        xge_p, 2048);
    // 7) inter biGRU
    k_gru_inter<<<64, 256, sm_inter>>>((float*)xge_p, Whh_e, bhh_e, (float*)ioe_p);
    // 8) sentence attention partial logits (NO softmax)
    k_gemm4<256, true, false, false><<<dim3(32, 2), 256, sm_gemm>>>(
        nullptr, (float*)ioe_p, (uint16_t*)ww_p + 65536, b_e, proj_e, a2_p, 2048);
    // 9) doc vector + final linear
    k_doc_final<<<64, 256>>>((float*)a2_p, (float*)ioe_p, Wf, bf, outp);
}

// round 16
// speedup vs baseline: 1.7940x; 1.0507x over previous
#include <cuda_runtime.h>
#include <cuda_fp16.h>
#include <math.h>
#include <stdint.h>

#define S_  32
#define T_  64
#define B_  64
#define C_  5
#define VOCAB_ 32000

// ---------------- scratch (device globals; no allocation) ----------------
__device__ uint16_t g_xg_h[(size_t)2*S_*T_*B_*384]; // fp16 [dir][row(s,t,b)][384]
__device__ uint16_t g_io_h[(size_t)S_*T_*B_*256];   // fp16 [s][t][b][256] fwd|bwd
__device__ float g_a1p[2*S_*T_*B_];                 // 2 partial planes
__device__ float g_sent[S_*B_*256];
__device__ float g_xg_inter[2*S_*B_*384];
__device__ float g_inter_out[S_*B_*256];
__device__ float g_a2p[2*S_*B_];
// fp16 preconversions
__device__ uint16_t g_emb_h[(size_t)VOCAB_*128];    // embed table half
__device__ uint16_t g_wihA_h[768*128];              // Wih_a half [col][k]
__device__ uint16_t g_wihE_h[768*256];              // Wih_e half [col][k]
__device__ uint16_t g_ww_h[2*256*256];              // WW_a/WW_e transposed half [n][k]

__device__ __forceinline__ float sigm(float x) { return 1.f / (1.f + expf(-x)); }

__device__ __forceinline__ uint32_t f2h2(float x, float y) {
    __half2 h = __floats2half2_rn(x, y);
    return *(uint32_t*)&h;
}
__device__ __forceinline__ float2 h2f2(uint32_t u) {
    return __half22float2(*(__half2*)&u);
}

__device__ __forceinline__ void mma_f16(float c[4],
                                        uint32_t a0, uint32_t a1, uint32_t a2, uint32_t a3,
                                        uint32_t b0, uint32_t b1) {
    asm volatile(
        "mma.sync.aligned.m16n8k16.row.col.f32.f16.f16.f32 "
        "{%0,%1,%2,%3}, {%4,%5,%6,%7}, {%8,%9}, {%0,%1,%2,%3};"
        : "+f"(c[0]), "+f"(c[1]), "+f"(c[2]), "+f"(c[3])
        : "r"(a0), "r"(a1), "r"(a2), "r"(a3), "r"(b0), "r"(b1));
}

// cp.async helpers (16B)
__device__ __forceinline__ void cp16(uint32_t dst_sm, const void* src) {
    asm volatile("cp.async.ca.shared.global [%0], [%1], 16;" :: "r"(dst_sm), "l"(src));
}
#define CP_COMMIT() asm volatile("cp.async.commit_group;" ::: "memory")
#define CP_WAIT0()  asm volatile("cp.async.wait_group 0;" ::: "memory")
#define CP_WAIT1()  asm volatile("cp.async.wait_group 1;" ::: "memory")

// ---- prep kernels: one-time fp16 conversions ------------------------------
__global__ void k_prep_h(const float* __restrict__ in, uint16_t* __restrict__ out) {
    size_t q = ((size_t)blockIdx.x * 256 + threadIdx.x) * 8;
    float4 v0 = *(const float4*)(in + q);
    float4 v1 = *(const float4*)(in + q + 4);
    uint4 u = make_uint4(f2h2(v0.x, v0.y), f2h2(v0.z, v0.w),
                         f2h2(v1.x, v1.y), f2h2(v1.z, v1.w));
    *(uint4*)(out + q) = u;
}
__global__ void k_prep_ww_h(const float* __restrict__ Wa, const float* __restrict__ We,
                            uint16_t* __restrict__ out) {
    int idx = blockIdx.x * 256 + threadIdx.x;       // 0..65535
    const float* W = blockIdx.y ? We : Wa;
    int n = idx >> 8, h = idx & 255;
    __half v = __float2half_rn(W[h * 256 + n]);
    out[blockIdx.y * 65536 + n * 256 + h] = *(uint16_t*)&v;
}

// ============ unified fp16 tensor GEMM: 64x128 tiles, 3 blocks/SM =========
// AHALF: A preconverted half -> cp.async double-buffered pipeline.
template<int KDIM, bool ATTN, bool AHALF, bool OH>
__global__ __launch_bounds__(256, 3) void k_gemm4(const int* __restrict__ tokens,
                                                  const void* __restrict__ Av,
                                                  const uint16_t* __restrict__ Wt,
                                                  const float* __restrict__ bias,
                                                  const float* __restrict__ proj,
                                                  void* __restrict__ outv,
                                                  int nrows) {
    constexpr int NC = KDIM / 64;
    extern __shared__ uint32_t usm[];
    // AHALF: double buffers [2][64*36 + 128*36]; else single buffer.
    __shared__ int toks[64];
    __shared__ float part_sm[4][65];
    const int rb = blockIdx.x, cb = blockIdx.y;
    const int tid = threadIdx.x;
    const int lane = tid & 31, wid = tid >> 5;
    const int wm = wid >> 2, wn = wid & 3;   // 2 (M) x 4 (N)
    const int grp = lane >> 2, t4 = lane & 3;

    if (tokens) {
        if (tid < 64) toks[tid] = tokens[rb * 64 + tid];
        __syncthreads();
    }

    float acc[2][4][4];
#pragma unroll
    for (int i = 0; i < 2; i++)
#pragma unroll
        for (int j = 0; j < 4; j++)
#pragma unroll
            for (int r = 0; r < 4; r++) acc[i][j][r] = 0.f;

    if (AHALF) {
        // ---------- pipelined path: cp.async double-buffer ----------
        const int BUF = 64 * 36 + 128 * 36;   // words per buffer
        uint32_t sbase;
        asm("{ .reg .u64 t; cvta.to.shared.u64 t, %1; cvt.u32.u64 %0, t; }"
            : "=r"(sbase) : "l"(usm));

        auto issue = [&](int kc, int buf) {
            uint32_t* As = usm + buf * BUF;
            uint32_t* Bs = As + 64 * 36;
            for (int q = tid; q < 64 * 8; q += 256) {
                int r = q >> 3, u = q & 7;
                size_t rowbase = tokens ? (size_t)toks[r] * KDIM
                                        : (size_t)(rb * 64 + r) * KDIM;
                cp16(sbase + (uint32_t)((As - usm) + r * 36 + u * 4) * 4,
                     (const uint16_t*)Av + rowbase + kc * 64 + u * 8);
            }
            for (int q = tid; q < 128 * 8; q += 256) {
                int n = q >> 3, u = q & 7;
                cp16(sbase + (uint32_t)((Bs - usm) + n * 36 + u * 4) * 4,
                     Wt + (size_t)(cb * 128 + n) * KDIM + kc * 64 + u * 8);
            }
            CP_COMMIT();
        };

        issue(0, 0);
#pragma unroll
        for (int kc = 0; kc < NC; kc++) {
            if (kc + 1 < NC) {
                issue(kc + 1, (kc + 1) & 1);
                CP_WAIT1();
            } else {
                CP_WAIT0();
            }
            __syncthreads();
            uint32_t* As = usm + (kc & 1) * BUF;
            uint32_t* Bs = As + 64 * 36;
#pragma unroll
            for (int ks = 0; ks < 4; ks++) {
                const int kb = ks * 8;
                uint32_t a[2][4], b[4][2];
#pragma unroll
                for (int i = 0; i < 2; i++) {
                    int row = wm * 32 + i * 16 + grp;
                    a[i][0] = As[row * 36 + kb + t4];
                    a[i][1] = As[(row + 8) * 36 + kb + t4];
                    a[i][2] = As[row * 36 + kb + 4 + t4];
                    a[i][3] = As[(row + 8) * 36 + kb + 4 + t4];
                }
#pragma unroll
                for (int j = 0; j < 4; j++) {
                    int n = wn * 32 + j * 8 + grp;
                    b[j][0] = Bs[n * 36 + kb + t4];
                    b[j][1] = Bs[n * 36 + kb + 4 + t4];
                }
#pragma unroll
                for (int i = 0; i < 2; i++)
#pragma unroll
                    for (int j = 0; j < 4; j++)
                        mma_f16(acc[i][j], a[i][0], a[i][1], a[i][2], a[i][3],
                                b[j][0], b[j][1]);
            }
            __syncthreads();
        }
    } else {
        // ---------- legacy path (fp32 A, converted on load) ----------
        uint32_t* As = usm;
        uint32_t* Bs = usm + 64 * 36;
#pragma unroll
        for (int kc = 0; kc < NC; kc++) {
            if (kc) __syncthreads();
            for (int q = tid; q < 64 * 8; q += 256) {
                int r = q >> 3, u = q & 7;
                size_t rowbase = (size_t)(rb * 64 + r) * KDIM;
                const float* src = (const float*)Av + rowbase + kc * 64 + u * 8;
                float4 v0 = *(const float4*)src;
                float4 v1 = *(const float4*)(src + 4);
                *(uint4*)(As + r * 36 + u * 4) =
                    make_uint4(f2h2(v0.x, v0.y), f2h2(v0.z, v0.w),
                               f2h2(v1.x, v1.y), f2h2(v1.z, v1.w));
            }
            for (int q = tid; q < 128 * 8; q += 256) {
                int n = q >> 3, u = q & 7;
                uint4 v = *(const uint4*)(Wt + (size_t)(cb * 128 + n) * KDIM + kc * 64 + u * 8);
                *(uint4*)(Bs + n * 36 + u * 4) = v;
            }
            __syncthreads();
#pragma unroll
            for (int ks = 0; ks < 4; ks++) {
                const int kb = ks * 8;
                uint32_t a[2][4], b[4][2];
#pragma unroll
                for (int i = 0; i < 2; i++) {
                    int row = wm * 32 + i * 16 + grp;
                    a[i][0] = As[row * 36 + kb + t4];
                    a[i][1] = As[(row + 8) * 36 + kb + t4];
                    a[i][2] = As[row * 36 + kb + 4 + t4];
                    a[i][3] = As[(row + 8) * 36 + kb + 4 + t4];
                }
#pragma unroll
                for (int j = 0; j < 4; j++) {
                    int n = wn * 32 + j * 8 + grp;
                    b[j][0] = Bs[n * 36 + kb + t4];
                    b[j][1] = Bs[n * 36 + kb + 4 + t4];
                }
#pragma unroll
                for (int i = 0; i < 2; i++)
#pragma unroll
                    for (int j = 0; j < 4; j++)
                        mma_f16(acc[i][j], a[i][0], a[i][1], a[i][2], a[i][3],
                                b[j][0], b[j][1]);
            }
        }
    }

    if (!ATTN) {
#pragma unroll
        for (int i = 0; i < 2; i++) {
            int row = rb * 64 + wm * 32 + i * 16 + grp;
#pragma unroll
            for (int j = 0; j < 4; j++) {
                int col = cb * 128 + wn * 32 + j * 8 + 2 * t4;
                int dir = (col >= 384) ? 1 : 0;
                int g = col - dir * 384;
                float b0v = bias[col], b1v = bias[col + 1];
                if (OH) {
                    uint16_t* o16 = (uint16_t*)outv;
                    *(uint32_t*)&o16[((size_t)dir * nrows + row) * 384 + g] =
                        f2h2(acc[i][j][0] + b0v, acc[i][j][1] + b1v);
                    *(uint32_t*)&o16[((size_t)dir * nrows + row + 8) * 384 + g] =
                        f2h2(acc[i][j][2] + b0v, acc[i][j][3] + b1v);
                } else {
                    float* of = (float*)outv;
                    *(float2*)&of[((size_t)dir * nrows + row) * 384 + g] =
                        make_float2(acc[i][j][0] + b0v, acc[i][j][1] + b1v);
                    *(float2*)&of[((size_t)dir * nrows + row + 8) * 384 + g] =
                        make_float2(acc[i][j][2] + b0v, acc[i][j][3] + b1v);
                }
            }
        }
    } else {
        float* logits = (float*)outv;
        float rsum[2][2];
#pragma unroll
        for (int i = 0; i < 2; i++) { rsum[i][0] = 0.f; rsum[i][1] = 0.f; }
#pragma unroll
        for (int j = 0; j < 4; j++) {
            int col = cb * 128 + wn * 32 + j * 8 + 2 * t4;
            float pv0 = proj[col], pv1 = proj[col + 1];
            float bv0 = bias[col], bv1 = bias[col + 1];
#pragma unroll
            for (int i = 0; i < 2; i++) {
                rsum[i][0] += pv0 * tanhf(acc[i][j][0] + bv0) + pv1 * tanhf(acc[i][j][1] + bv1);
                rsum[i][1] += pv0 * tanhf(acc[i][j][2] + bv0) + pv1 * tanhf(acc[i][j][3] + bv1);
            }
        }
#pragma unroll
        for (int i = 0; i < 2; i++)
#pragma unroll
            for (int sr = 0; sr < 2; sr++) {
                float v = rsum[i][sr];
                v += __shfl_xor_sync(0xffffffffu, v, 1);
                v += __shfl_xor_sync(0xffffffffu, v, 2);
                if (t4 == 0) part_sm[wn][wm * 32 + i * 16 + sr * 8 + grp] = v;
            }
        __syncthreads();
        if (tid < 64)
            logits[(size_t)cb * nrows + rb * 64 + tid] =
                part_sm[0][tid] + part_sm[1][tid] + part_sm[2][tid] + part_sm[3][tid];
    }
}

// ========== K3a: intra biGRU, fp16 tensor recurrence, 64 steps ============
// 16 batch rows / block -> grid 256, 2 blocks/SM (epilogue overlaps mma).
__global__ __launch_bounds__(256, 2) void k_gru_intra_t(const uint16_t* __restrict__ xg,
                                                        const float* __restrict__ Whh,
                                                        const float* __restrict__ bhh,
                                                        uint16_t* __restrict__ out) {
    extern __shared__ uint32_t usm[];
    uint32_t* Ws = usm;                       // 384 x 68 words (half2 [n][kw])
    float* hsm = (float*)(usm + 384 * 68);    // 16 x 132 fp32
    const int bx = blockIdx.x;
    const int dir = bx >> 7, s = (bx >> 2) & 31, qt = bx & 3;
    const int b0 = qt * 16;
    const int tid = threadIdx.x;
    const int lane = tid & 31, w = tid >> 5;
    const int grp = lane >> 2, t4 = lane & 3;

    for (int idx = tid; idx < 384 * 64; idx += 256) {
        int n = idx >> 6, kw = idx & 63;
        const float* p = Whh + dir * 384 * 128 + n * 128 + kw * 2;
        Ws[n * 68 + kw] = f2h2(p[0], p[1]);
    }
    for (int idx = tid; idx < 16 * 132; idx += 256) hsm[idx] = 0.f;
    __syncthreads();

    const int j2 = 16 * w + 2 * t4;
    float br[2][2], bz[2][2], bn[2][2];
#pragma unroll
    for (int jj = 0; jj < 2; jj++)
#pragma unroll
        for (int c = 0; c < 2; c++) {
            int j = j2 + 8 * jj + c;
            br[jj][c] = bhh[dir * 384 + j];
            bz[jj][c] = bhh[dir * 384 + 128 + j];
            bn[jj][c] = bhh[dir * 384 + 256 + j];
        }

    for (int tt = 0; tt < 64; tt++) {
        const int t = dir ? (63 - tt) : tt;
        const uint16_t* xgbase = xg + ((size_t)dir * 131072 + ((s * 64 + t) * 64 + b0)) * 384;

        float2 xr[2][2][3];
#pragma unroll
        for (int sr = 0; sr < 2; sr++) {
            const uint16_t* p = xgbase + (size_t)(grp + 8 * sr) * 384 + j2;
#pragma unroll
            for (int jj = 0; jj < 2; jj++) {
                xr[sr][jj][0] = h2f2(*(const uint32_t*)(p + 8 * jj));
                xr[sr][jj][1] = h2f2(*(const uint32_t*)(p + 128 + 8 * jj));
                xr[sr][jj][2] = h2f2(*(const uint32_t*)(p + 256 + 8 * jj));
            }
        }

        float acc[6][4];
#pragma unroll
        for (int nt = 0; nt < 6; nt++)
#pragma unroll
            for (int r = 0; r < 4; r++) acc[nt][r] = 0.f;

#pragma unroll
        for (int ks = 0; ks < 8; ks++) {
            uint32_t ah[4];
            {
                float2 p0 = *(const float2*)&hsm[grp * 132 + 16 * ks + 2 * t4];
                float2 p1 = *(const float2*)&hsm[(8 + grp) * 132 + 16 * ks + 2 * t4];
                float2 p2 = *(const float2*)&hsm[grp * 132 + 16 * ks + 8 + 2 * t4];
                float2 p3 = *(const float2*)&hsm[(8 + grp) * 132 + 16 * ks + 8 + 2 * t4];
                ah[0] = f2h2(p0.x, p0.y);
                ah[1] = f2h2(p1.x, p1.y);
                ah[2] = f2h2(p2.x, p2.y);
                ah[3] = f2h2(p3.x, p3.y);
            }
            const int kb = ks * 8;
#pragma unroll
            for (int nt = 0; nt < 6; nt++) {
                int n = 128 * (nt >> 1) + 16 * w + 8 * (nt & 1) + grp;
                uint32_t brg0 = Ws[n * 68 + kb + t4];
                uint32_t brg1 = Ws[n * 68 + kb + 4 + t4];
                mma_f16(acc[nt], ah[0], ah[1], ah[2], ah[3], brg0, brg1);
            }
        }

        float hn[2][2][2];
#pragma unroll
        for (int sr = 0; sr < 2; sr++) {
            int row = 8 * sr + grp;
#pragma unroll
            for (int jj = 0; jj < 2; jj++) {
                float2 ho = *(const float2*)&hsm[row * 132 + j2 + 8 * jj];
                float r0 = sigm(xr[sr][jj][0].x + acc[jj][2 * sr] + br[jj][0]);
                float r1 = sigm(xr[sr][jj][0].y + acc[jj][2 * sr + 1] + br[jj][1]);
                float z0 = sigm(xr[sr][jj][1].x + acc[2 + jj][2 * sr] + bz[jj][0]);
                float z1 = sigm(xr[sr][jj][1].y + acc[2 + jj][2 * sr + 1] + bz[jj][1]);
                float n0 = tanhf(xr[sr][jj][2].x + r0 * (acc[4 + jj][2 * sr] + bn[jj][0]));
                float n1 = tanhf(xr[sr][jj][2].y + r1 * (acc[4 + jj][2 * sr + 1] + bn[jj][1]));
                float h0 = (1.f - z0) * n0 + z0 * ho.x;
                float h1 = (1.f - z1) * n1 + z1 * ho.y;
                hn[sr][jj][0] = h0;
                hn[sr][jj][1] = h1;
                *(uint32_t*)&out[(((size_t)(s * 64 + t)) * 64 + b0 + row) * 256 +
                                 dir * 128 + j2 + 8 * jj] = f2h2(h0, h1);
            }
        }
        __syncthreads();
#pragma unroll
        for (int sr = 0; sr < 2; sr++) {
            int row = 8 * sr + grp;
#pragma unroll
            for (int jj = 0; jj < 2; jj++)
                *(float2*)&hsm[row * 132 + j2 + 8 * jj] =
                    make_float2(hn[sr][jj][0], hn[sr][jj][1]);
        }
        __syncthreads();
    }
}

// ---------------- K3b: inter biGRU (small, SIMT) --------------------------
__global__ void k_gru_inter(const float* __restrict__ xg,
                            const float* __restrict__ Whh,
                            const float* __restrict__ bhh,
                            float* __restrict__ out) {
    extern __shared__ float sm[];
    float* Ws = sm;              // 384*133
    float* hs = sm + 384 * 133;  // 2*132
    const int bx = blockIdx.x;
    const int dir = bx >> 5;
    const int b0 = (bx & 31) * 2;
    const int tid = threadIdx.x;
    const int bl = tid >> 7;
    const int j = tid & 127;

    for (int idx = tid; idx < 384 * 128; idx += 256) {
        int row = idx >> 7, k = idx & 127;
        Ws[row * 133 + k] = Whh[dir * 384 * 128 + idx];
    }
    for (int idx = tid; idx < 2 * 132; idx += 256) hs[idx] = 0.f;
    __syncthreads();

    const float br = bhh[dir * 384 + j];
    const float bz = bhh[dir * 384 + 128 + j];
    const float bn = bhh[dir * 384 + 256 + j];

    for (int tt = 0; tt < 32; tt++) {
        const int sstep = dir ? (31 - tt) : tt;
        float ar = 0.f, az = 0.f, an = 0.f;
#pragma unroll 4
        for (int k = 0; k < 128; k++) {
            float hv = hs[bl * 132 + k];
            int ro = j * 133 + k;
            ar = fmaf(hv, Ws[ro], ar);
            az = fmaf(hv, Ws[ro + 128 * 133], az);
            an = fmaf(hv, Ws[ro + 256 * 133], an);
        }
        const int b = b0 + bl;
        const float* xr = xg + (((size_t)dir * 32 + sstep) * 64 + b) * 384;
        float r = sigm(xr[j] + ar + br);
        float z = sigm(xr[128 + j] + az + bz);
        float n = tanhf(xr[256 + j] + r * (an + bn));
        float ho = hs[bl * 132 + j];
        float hv2 = (1.f - z) * n + z * ho;
        out[((size_t)sstep * 64 + b) * 256 + dir * 128 + j] = hv2;
        __syncthreads();
        hs[bl * 132 + j] = hv2;
        __syncthreads();
    }
}

// ------- softmax over t (sums 2 partial planes, writes plane 0) -----------
__global__ void k_softmax_t(float* __restrict__ a) {
    const int NP = S_ * T_ * B_;
    int gid = blockIdx.x * blockDim.x + threadIdx.x;
    if (gid >= S_ * B_) return;
    int s = gid >> 6, b = gid & 63;
    size_t base = (size_t)s * 4096 + b;
    float mx = -1e30f;
    for (int t = 0; t < 64; t++) {
        float v = a[base + t * 64] + a[NP + base + t * 64];
        mx = fmaxf(mx, v);
    }
    float sum = 0.f;
    for (int t = 0; t < 64; t++) {
        float v = a[base + t * 64] + a[NP + base + t * 64];
        sum += expf(v - mx);
    }
    float inv = 1.f / sum;
    for (int t = 0; t < 64; t++) {
        float v = a[base + t * 64] + a[NP + base + t * 64];
        a[base + t * 64] = expf(v - mx) * inv;
    }
}

// ---------------- sentence vectors: sum_t a1 * X (X fp16) ------------------
__global__ void k_sent(const float* __restrict__ a1,
                       const uint16_t* __restrict__ X,
                       float* __restrict__ sent) {
    const int s = blockIdx.x, bg = blockIdx.y;
    const int h = threadIdx.x;
    float acc[8];
#pragma unroll
    for (int ib = 0; ib < 8; ib++) acc[ib] = 0.f;
    for (int t = 0; t < 64; t++) {
#pragma unroll
        for (int ib = 0; ib < 8; ib++) {
            int b = bg * 8 + ib;
            size_t row = (size_t)s * 4096 + (size_t)t * 64 + b;
            __half hv = *(const __half*)&X[row * 256 + h];
            acc[ib] = fmaf(a1[row], __half2float(hv), acc[ib]);
        }
    }
#pragma unroll
    for (int ib = 0; ib < 8; ib++)
        sent[((size_t)s * 64 + bg * 8 + ib) * 256 + h] = acc[ib];
}

// --------- doc vector + final linear (sums 2 partial a2 planes) -----------
__global__ void k_doc_final(const float* __restrict__ a2,
                            const float* __restrict__ Xo,
                            const float* __restrict__ Wf,
                            const float* __restrict__ bf,
                            float* __restrict__ outp) {
    __shared__ float red[256];
    const int b = blockIdx.x, h = threadIdx.x;
    float dh = 0.f;
    for (int s2 = 0; s2 < 32; s2++) {
        size_t row = (size_t)s2 * 64 + b;
        float av = a2[row] + a2[S_ * B_ + row];
        dh = fmaf(av, Xo[row * 256 + h], dh);
    }
    for (int c = 0; c < C_; c++) {
        red[h] = dh * Wf[c * 256 + h];
        __syncthreads();
        for (int off = 128; off > 0; off >>= 1) {
            if (h < off) red[h] += red[h + off];
            __syncthreads();
        }
        if (h == 0) outp[b * C_ + c] = red[0] + bf[c];
        __syncthreads();
    }
}

// ---------------- launch ---------------------------------------------------
extern "C" void kernel_launch(void* const* d_in, const int* in_sizes, int n_in,
                              void* d_out, int out_size) {
    const int*   tokens = (const int*)d_in[0];
    const float* embed  = (const float*)d_in[1];
    const float* Wih_a  = (const float*)d_in[2];
    const float* Whh_a  = (const float*)d_in[3];
    const float* bih_a  = (const float*)d_in[4];
    const float* bhh_a  = (const float*)d_in[5];
    const float* WW_a   = (const float*)d_in[6];
    const float* b_a    = (const float*)d_in[7];
    const float* proj_a = (const float*)d_in[8];
    const float* Wih_e  = (const float*)d_in[9];
    const float* Whh_e  = (const float*)d_in[10];
    const float* bih_e  = (const float*)d_in[11];
    const float* bhh_e  = (const float*)d_in[12];
    const float* WW_e   = (const float*)d_in[13];
    const float* b_e    = (const float*)d_in[14];
    const float* proj_e = (const float*)d_in[15];
    const float* Wf     = (const float*)d_in[16];
    const float* bf     = (const float*)d_in[17];
    float* outp = (float*)d_out;

    void *xgh_p, *ioh_p, *a1_p, *sent_p, *xge_p, *ioe_p, *a2_p;
    void *embh_p, *wihA_p, *wihE_p, *ww_p;
    cudaGetSymbolAddress(&xgh_p, g_xg_h);
    cudaGetSymbolAddress(&ioh_p, g_io_h);
    cudaGetSymbolAddress(&a1_p, g_a1p);
    cudaGetSymbolAddress(&sent_p, g_sent);
    cudaGetSymbolAddress(&xge_p, g_xg_inter);
    cudaGetSymbolAddress(&ioe_p, g_inter_out);
    cudaGetSymbolAddress(&a2_p, g_a2p);
    cudaGetSymbolAddress(&embh_p, g_emb_h);
    cudaGetSymbolAddress(&wihA_p, g_wihA_h);
    cudaGetSymbolAddress(&wihE_p, g_wihE_h);
    cudaGetSymbolAddress(&ww_p, g_ww_h);

    const int sm_pipe  = 2 * (64 * 36 + 128 * 36) * 4;  // 55296 (AHALF pipelined)
    const int sm_gemm  = (64 * 36 + 128 * 36) * 4;      // 27648 (legacy)
    const int sm_intra = (384 * 68 + 16 * 132) * 4;     // 112896
    const int sm_inter = (384 * 133 + 2 * 132) * 4;
    cudaFuncSetAttribute((const void*)k_gemm4<128, false, true, true>,
                         cudaFuncAttributeMaxDynamicSharedMemorySize, sm_pipe);
    cudaFuncSetAttribute((const void*)k_gemm4<256, true, true, false>,
                         cudaFuncAttributeMaxDynamicSharedMemorySize, sm_pipe);
    cudaFuncSetAttribute((const void*)k_gemm4<256, false, false, false>,
                         cudaFuncAttributeMaxDynamicSharedMemorySize, sm_gemm);
    cudaFuncSetAttribute((const void*)k_gemm4<256, true, false, false>,
                         cudaFuncAttributeMaxDynamicSharedMemorySize, sm_gemm);
    cudaFuncSetAttribute(k_gru_intra_t, cudaFuncAttributeMaxDynamicSharedMemorySize, sm_intra);
    cudaFuncSetAttribute(k_gru_inter, cudaFuncAttributeMaxDynamicSharedMemorySize, sm_inter);

    // 0) one-time fp16 conversions
    k_prep_h<<<2000, 256>>>(embed, (uint16_t*)embh_p);
    k_prep_h<<<48, 256>>>(Wih_a, (uint16_t*)wihA_p);
    k_prep_h<<<96, 256>>>(Wih_e, (uint16_t*)wihE_p);
    k_prep_ww_h<<<dim3(256, 2), 256>>>(WW_a, WW_e, (uint16_t*)ww_p);
    // 1) intra input gates: gathered fp16 GEMM (cp.async pipeline) -> fp16 xg
    k_gemm4<128, false, true, true><<<dim3(2048, 6), 256, sm_pipe>>>(
        tokens, (uint16_t*)embh_p, (uint16_t*)wihA_p, bih_a, nullptr,
        xgh_p, 131072);
    // 2) intra biGRU (fp16 tensor recurrence; 16 rows/block, 2 blocks/SM)
    k_gru_intra_t<<<256, 256, sm_intra>>>((uint16_t*)xgh_p, Whh_a, bhh_a,
                                          (uint16_t*)ioh_p);
    // 3) word attention partial logits (cp.async pipeline; 2 col-halves)
    k_gemm4<256, true, true, false><<<dim3(2048, 2), 256, sm_pipe>>>(
        nullptr, (uint16_t*)ioh_p, (uint16_t*)ww_p, b_a, proj_a, a1_p, 131072);
    // 4) softmax over tokens (sums planes)
    k_softmax_t<<<8, 256>>>((float*)a1_p);
    // 5) sentence vectors (fp16 X)
    k_sent<<<dim3(32, 8), 256>>>((float*)a1_p, (uint16_t*)ioh_p, (float*)sent_p);
    // 6) inter input gates: rows = 2048 (fp32 in/out, legacy path)
    k_gemm4<256, false, false, false><<<dim3(32, 6), 256, sm_gemm>>>(
        nullptr, (float*)sent_p, (uint16_t*)wihE_p, bih_e, nullptr,
        xge_p, 2048);
    // 7) inter biGRU
    k_gru_inter<<<64, 256, sm_inter>>>((float*)xge_p, Whh_e, bhh_e, (float*)ioe_p);
    // 8) sentence attention partial logits (NO softmax, legacy path)
    k_gemm4<256, true, false, false><<<dim3(32, 2), 256, sm_gemm>>>(
        nullptr, (float*)ioe_p, (uint16_t*)ww_p + 65536, b_e, proj_e, a2_p, 2048);
    // 9) doc vector + final linear
    k_doc_final<<<64, 256>>>((float*)a2_p, (float*)ioe_p, Wf, bf, outp);
}